// round 1
// baseline (speedup 1.0000x reference)
#include <cuda_runtime.h>
#include <cuda_bf16.h>
#include <cstdint>
#include <cstddef>

// Problem dims
#define B_ 256
#define T_ 512
#define D_ 512
#define H_ 1024
#define O_ 512

constexpr int    BH  = B_ * H_;                      // 262144
constexpr size_t BTH = (size_t)B_ * T_ * H_;         // 134217728
constexpr size_t BTO = (size_t)B_ * T_ * O_;         // 67108864

// ---------------- scratch (static __device__ arrays; no runtime alloc) ----
__device__ float         g_P[BTH];                           // x @ W_xh, fp32
__device__ __nv_bfloat16 g_Hhi[(size_t)(T_ + 1) * BH];       // split h, hi plane
__device__ __nv_bfloat16 g_Hlo[(size_t)(T_ + 1) * BH];       // split h, lo plane
__device__ __nv_bfloat16 g_Wxh_hi[D_ * H_], g_Wxh_lo[D_ * H_];
__device__ __nv_bfloat16 g_Whh_hi[H_ * H_], g_Whh_lo[H_ * H_];
__device__ __nv_bfloat16 g_Why_hi[H_ * O_], g_Why_lo[H_ * O_];

// ---------------- shared-mem tile geometry --------------------------------
// CTA tile 64x64, K-tile 32 real k. 4 warps (2x2), each warp 32x32:
// 2 m-frags (16) x 4 n-frags (8), mma.sync m16n8k16 bf16.
constexpr int SA = 40;   // padded smem row stride (elems), even (b32 loads ok)

__device__ __forceinline__ void mma_bf16(float* c, const uint32_t* a, const uint32_t* b) {
    asm volatile(
        "mma.sync.aligned.m16n8k16.row.col.f32.bf16.bf16.f32 "
        "{%0,%1,%2,%3}, {%4,%5,%6,%7}, {%8,%9}, {%0,%1,%2,%3};\n"
        : "+f"(c[0]), "+f"(c[1]), "+f"(c[2]), "+f"(c[3])
        : "r"(a[0]), "r"(a[1]), "r"(a[2]), "r"(a[3]), "r"(b[0]), "r"(b[1]));
}

// 3-term split-bf16 accumulation over one 64x64x32 smem tile:
// acc += Ahi*Bhi + Ahi*Blo + Alo*Bhi   (lo*lo dropped, ~2^-18 rel)
__device__ __forceinline__ void compute_tile(
    const __nv_bfloat16* sAhi, const __nv_bfloat16* sAlo,
    const __nv_bfloat16* sBhi, const __nv_bfloat16* sBlo,
    float acc[2][4][4], int wm, int wn, int g, int tg)
{
#pragma unroll
    for (int ks = 0; ks < 32; ks += 16) {
        uint32_t ahi[2][4], alo[2][4], bhi[4][2], blo[4][2];
#pragma unroll
        for (int mf = 0; mf < 2; mf++) {
            int off = (wm + mf * 16 + g) * SA + ks + tg * 2;
            ahi[mf][0] = *(const uint32_t*)(sAhi + off);
            ahi[mf][1] = *(const uint32_t*)(sAhi + off + 8 * SA);
            ahi[mf][2] = *(const uint32_t*)(sAhi + off + 8);
            ahi[mf][3] = *(const uint32_t*)(sAhi + off + 8 * SA + 8);
            alo[mf][0] = *(const uint32_t*)(sAlo + off);
            alo[mf][1] = *(const uint32_t*)(sAlo + off + 8 * SA);
            alo[mf][2] = *(const uint32_t*)(sAlo + off + 8);
            alo[mf][3] = *(const uint32_t*)(sAlo + off + 8 * SA + 8);
        }
#pragma unroll
        for (int nf = 0; nf < 4; nf++) {
            int off = (wn + nf * 8 + g) * SA + ks + tg * 2;
            bhi[nf][0] = *(const uint32_t*)(sBhi + off);
            bhi[nf][1] = *(const uint32_t*)(sBhi + off + 8);
            blo[nf][0] = *(const uint32_t*)(sBlo + off);
            blo[nf][1] = *(const uint32_t*)(sBlo + off + 8);
        }
#pragma unroll
        for (int mf = 0; mf < 2; mf++)
#pragma unroll
            for (int nf = 0; nf < 4; nf++) {
                mma_bf16(acc[mf][nf], ahi[mf], bhi[nf]);
                mma_bf16(acc[mf][nf], ahi[mf], blo[nf]);
                mma_bf16(acc[mf][nf], alo[mf], bhi[nf]);
            }
    }
}

// Load a 64x32 bf16 A tile (row-major, lda elems) into padded smem.
__device__ __forceinline__ void load_A_bf16(
    __nv_bfloat16* sA, const __nv_bfloat16* g, int lda, int tid)
{
#pragma unroll
    for (int i = 0; i < 8; i++) {
        int idx = i * 128 + tid;          // 1024 u32 total
        int r = idx >> 4, c2 = idx & 15;  // 16 u32 per row
        *(uint32_t*)(sA + r * SA + c2 * 2) =
            *(const uint32_t*)(g + (size_t)r * lda + c2 * 2);
    }
}

// Load a 32x64 weight tile [k][n] (row-major, ldb elems), transposed into
// smem as [n][k] (k-contiguous, matching B-fragment layout).
__device__ __forceinline__ void load_B(
    __nv_bfloat16* sB, const __nv_bfloat16* g, int ldb, int tid)
{
#pragma unroll
    for (int i = 0; i < 16; i++) {
        int idx = i * 128 + tid;          // 2048 elems
        int k = idx >> 6, n = idx & 63;
        sB[n * SA + k] = g[(size_t)k * ldb + n];
    }
}

// ---------------- kernel 1: P = split(X) @ split(W_xh) --------------------
__global__ __launch_bounds__(128) void gemm_P_kernel(const float* __restrict__ X)
{
    __shared__ __align__(16) __nv_bfloat16 sAhi[64 * SA], sAlo[64 * SA];
    __shared__ __align__(16) __nv_bfloat16 sBhi[64 * SA], sBlo[64 * SA];
    int tid = threadIdx.x;
    int lane = tid & 31, warp = tid >> 5;
    int g = lane >> 2, tg = lane & 3;
    int wm = (warp >> 1) * 32, wn = (warp & 1) * 32;
    int n0 = blockIdx.x * 64;
    size_t m0 = (size_t)blockIdx.y * 64;

    float acc[2][4][4];
#pragma unroll
    for (int a = 0; a < 2; a++)
#pragma unroll
        for (int b = 0; b < 4; b++)
#pragma unroll
            for (int c = 0; c < 4; c++) acc[a][b][c] = 0.f;

    for (int k0 = 0; k0 < D_; k0 += 32) {
        const float* ga = X + m0 * D_ + k0;
#pragma unroll
        for (int i = 0; i < 16; i++) {
            int idx = i * 128 + tid;
            int r = idx >> 5, c = idx & 31;
            float v = ga[(size_t)r * D_ + c];
            __nv_bfloat16 hi = __float2bfloat16(v);
            sAhi[r * SA + c] = hi;
            sAlo[r * SA + c] = __float2bfloat16(v - __bfloat162float(hi));
        }
        load_B(sBhi, g_Wxh_hi + (size_t)k0 * H_ + n0, H_, tid);
        load_B(sBlo, g_Wxh_lo + (size_t)k0 * H_ + n0, H_, tid);
        __syncthreads();
        compute_tile(sAhi, sAlo, sBhi, sBlo, acc, wm, wn, g, tg);
        __syncthreads();
    }

#pragma unroll
    for (int mf = 0; mf < 2; mf++)
#pragma unroll
        for (int nf = 0; nf < 4; nf++) {
            size_t r = m0 + wm + mf * 16 + g;
            int c = n0 + wn + nf * 8 + tg * 2;
            g_P[r * H_ + c]           = acc[mf][nf][0];
            g_P[r * H_ + c + 1]       = acc[mf][nf][1];
            g_P[(r + 8) * H_ + c]     = acc[mf][nf][2];
            g_P[(r + 8) * H_ + c + 1] = acc[mf][nf][3];
        }
}

// ---------------- kernel 2: one recurrence step ---------------------------
// h_{t+1 slot} = tanh(P[:,t,:] + h_{t slot} @ W_hh), stored split.
__global__ __launch_bounds__(128) void step_kernel(int t)
{
    __shared__ __align__(16) __nv_bfloat16 sAhi[64 * SA], sAlo[64 * SA];
    __shared__ __align__(16) __nv_bfloat16 sBhi[64 * SA], sBlo[64 * SA];
    int tid = threadIdx.x;
    int lane = tid & 31, warp = tid >> 5;
    int g = lane >> 2, tg = lane & 3;
    int wm = (warp >> 1) * 32, wn = (warp & 1) * 32;
    int n0 = blockIdx.x * 64;
    int m0 = blockIdx.y * 64;   // batch rows

    float acc[2][4][4];
#pragma unroll
    for (int a = 0; a < 2; a++)
#pragma unroll
        for (int b = 0; b < 4; b++)
#pragma unroll
            for (int c = 0; c < 4; c++) acc[a][b][c] = 0.f;

    const __nv_bfloat16* Ahi = g_Hhi + (size_t)t * BH + (size_t)m0 * H_;
    const __nv_bfloat16* Alo = g_Hlo + (size_t)t * BH + (size_t)m0 * H_;

    for (int k0 = 0; k0 < H_; k0 += 32) {
        load_A_bf16(sAhi, Ahi + k0, H_, tid);
        load_A_bf16(sAlo, Alo + k0, H_, tid);
        load_B(sBhi, g_Whh_hi + (size_t)k0 * H_ + n0, H_, tid);
        load_B(sBlo, g_Whh_lo + (size_t)k0 * H_ + n0, H_, tid);
        __syncthreads();
        compute_tile(sAhi, sAlo, sBhi, sBlo, acc, wm, wn, g, tg);
        __syncthreads();
    }

#pragma unroll
    for (int mf = 0; mf < 2; mf++)
#pragma unroll
        for (int nf = 0; nf < 4; nf++) {
            int r = m0 + wm + mf * 16 + g;   // batch index
            int c = n0 + wn + nf * 8 + tg * 2;
#pragma unroll
            for (int e = 0; e < 4; e++) {
                int rr = r + (e >> 1) * 8;
                int cc = c + (e & 1);
                float arg = acc[mf][nf][e] + g_P[((size_t)rr * T_ + t) * H_ + cc];
                float h = tanhf(arg);
                __nv_bfloat16 hi = __float2bfloat16(h);
                size_t o = (size_t)(t + 1) * BH + (size_t)rr * H_ + cc;
                g_Hhi[o] = hi;
                g_Hlo[o] = __float2bfloat16(h - __bfloat162float(hi));
            }
        }
}

// ---------------- kernel 3: Y = H_all @ W_hy ------------------------------
// out row m = b*T + t  ->  A row from slot (t+1), batch b.
__global__ __launch_bounds__(128) void gemm_Y_kernel(float* __restrict__ out)
{
    __shared__ __align__(16) __nv_bfloat16 sAhi[64 * SA], sAlo[64 * SA];
    __shared__ __align__(16) __nv_bfloat16 sBhi[64 * SA], sBlo[64 * SA];
    int tid = threadIdx.x;
    int lane = tid & 31, warp = tid >> 5;
    int g = lane >> 2, tg = lane & 3;
    int wm = (warp >> 1) * 32, wn = (warp & 1) * 32;
    int n0 = blockIdx.x * 64;
    int m0 = blockIdx.y * 64;

    float acc[2][4][4];
#pragma unroll
    for (int a = 0; a < 2; a++)
#pragma unroll
        for (int b = 0; b < 4; b++)
#pragma unroll
            for (int c = 0; c < 4; c++) acc[a][b][c] = 0.f;

    for (int k0 = 0; k0 < H_; k0 += 32) {
#pragma unroll
        for (int i = 0; i < 8; i++) {
            int idx = i * 128 + tid;
            int r = idx >> 4, c2 = idx & 15;
            int m = m0 + r;
            int tt = m & (T_ - 1);
            int bb = m >> 9;                         // T_ = 512
            size_t base = (size_t)(tt + 1) * BH + (size_t)bb * H_ + k0 + c2 * 2;
            *(uint32_t*)(sAhi + r * SA + c2 * 2) = *(const uint32_t*)(g_Hhi + base);
            *(uint32_t*)(sAlo + r * SA + c2 * 2) = *(const uint32_t*)(g_Hlo + base);
        }
        load_B(sBhi, g_Why_hi + (size_t)k0 * O_ + n0, O_, tid);
        load_B(sBlo, g_Why_lo + (size_t)k0 * O_ + n0, O_, tid);
        __syncthreads();
        compute_tile(sAhi, sAlo, sBhi, sBlo, acc, wm, wn, g, tg);
        __syncthreads();
    }

#pragma unroll
    for (int mf = 0; mf < 2; mf++)
#pragma unroll
        for (int nf = 0; nf < 4; nf++) {
            size_t r = (size_t)m0 + wm + mf * 16 + g;
            int c = n0 + wn + nf * 8 + tg * 2;
            out[r * O_ + c]           = acc[mf][nf][0];
            out[r * O_ + c + 1]       = acc[mf][nf][1];
            out[(r + 8) * O_ + c]     = acc[mf][nf][2];
            out[(r + 8) * O_ + c + 1] = acc[mf][nf][3];
        }
}

// ---------------- small utility kernels -----------------------------------
__global__ void split_f32_kernel(const float* __restrict__ src,
                                 __nv_bfloat16* __restrict__ hi,
                                 __nv_bfloat16* __restrict__ lo, int n)
{
    int i = blockIdx.x * 256 + threadIdx.x;
    if (i < n) {
        float v = src[i];
        __nv_bfloat16 h = __float2bfloat16(v);
        hi[i] = h;
        lo[i] = __float2bfloat16(v - __bfloat162float(h));
    }
}

__global__ void final_h_kernel(float* __restrict__ out)
{
    int i = blockIdx.x * 256 + threadIdx.x;
    if (i < BH) {
        size_t o = (size_t)T_ * BH + i;
        out[BTO + i] = __bfloat162float(g_Hhi[o]) + __bfloat162float(g_Hlo[o]);
    }
}

// ---------------- launch ---------------------------------------------------
extern "C" void kernel_launch(void* const* d_in, const int* in_sizes, int n_in,
                              void* d_out, int out_size)
{
    (void)in_sizes; (void)n_in; (void)out_size;
    const float* x    = (const float*)d_in[0];
    const float* h0   = (const float*)d_in[1];
    const float* w_xh = (const float*)d_in[2];
    const float* w_hh = (const float*)d_in[3];
    const float* w_hy = (const float*)d_in[4];
    float* out = (float*)d_out;

    __nv_bfloat16 *p_Wxh_hi, *p_Wxh_lo, *p_Whh_hi, *p_Whh_lo,
                  *p_Why_hi, *p_Why_lo, *p_Hhi, *p_Hlo;
    cudaGetSymbolAddress((void**)&p_Wxh_hi, g_Wxh_hi);
    cudaGetSymbolAddress((void**)&p_Wxh_lo, g_Wxh_lo);
    cudaGetSymbolAddress((void**)&p_Whh_hi, g_Whh_hi);
    cudaGetSymbolAddress((void**)&p_Whh_lo, g_Whh_lo);
    cudaGetSymbolAddress((void**)&p_Why_hi, g_Why_hi);
    cudaGetSymbolAddress((void**)&p_Why_lo, g_Why_lo);
    cudaGetSymbolAddress((void**)&p_Hhi,    g_Hhi);
    cudaGetSymbolAddress((void**)&p_Hlo,    g_Hlo);

    // Split weights and h0 (slot 0 of the h ring).
    split_f32_kernel<<<(D_ * H_ + 255) / 256, 256>>>(w_xh, p_Wxh_hi, p_Wxh_lo, D_ * H_);
    split_f32_kernel<<<(H_ * H_ + 255) / 256, 256>>>(w_hh, p_Whh_hi, p_Whh_lo, H_ * H_);
    split_f32_kernel<<<(H_ * O_ + 255) / 256, 256>>>(w_hy, p_Why_hi, p_Why_lo, H_ * O_);
    split_f32_kernel<<<(BH + 255) / 256, 256>>>(h0, p_Hhi, p_Hlo, BH);

    // Phase 1: P = X @ W_xh for all timesteps (parallel).
    gemm_P_kernel<<<dim3(H_ / 64, (B_ * T_) / 64), 128>>>(x);

    // Phase 2: sequential recurrence over T steps.
    for (int t = 0; t < T_; t++)
        step_kernel<<<dim3(H_ / 64, B_ / 64), 128>>>(t);

    // Phase 3: Y = H_all @ W_hy (parallel), plus final h.
    gemm_Y_kernel<<<dim3(O_ / 64, (B_ * T_) / 64), 128>>>(out);
    final_h_kernel<<<(BH + 255) / 256, 256>>>(out);
}

// round 2
// speedup vs baseline: 2.2196x; 2.2196x over previous
#include <cuda_runtime.h>
#include <cuda_bf16.h>
#include <cstdint>
#include <cstddef>

// Problem dims
#define B_ 256
#define T_ 512
#define D_ 512
#define H_ 1024
#define O_ 512

constexpr int    BH  = B_ * H_;                      // 262144
constexpr size_t BTH = (size_t)B_ * T_ * H_;         // 134217728
constexpr size_t BTO = (size_t)B_ * T_ * O_;         // 67108864

// ---------------- scratch (static __device__ arrays; no runtime alloc) ----
__device__ float         g_P[BTH];                           // x @ W_xh, fp32, [t][b][h]
__device__ __nv_bfloat16 g_Hhi[(size_t)(T_ + 1) * BH];       // split h, hi plane
__device__ __nv_bfloat16 g_Hlo[(size_t)(T_ + 1) * BH];       // split h, lo plane
__device__ __nv_bfloat16 g_Wxh_hi[D_ * H_], g_Wxh_lo[D_ * H_];
__device__ __nv_bfloat16 g_Whh_hi[H_ * H_], g_Whh_lo[H_ * H_];
__device__ __nv_bfloat16 g_Why_hi[H_ * O_], g_Why_lo[H_ * O_];
__device__ unsigned      g_bar_count;                        // grid barrier counter

// ---------------- shared-mem tile geometry --------------------------------
constexpr int SA = 40;     // padded smem row stride for A/B 32-k tiles
constexpr int SW = 1032;   // padded row stride for resident W slab (k dim)

constexpr int NCTA_P = 128;            // persistent grid size
constexpr int SMEM_P_ELEMS = 2 * 32 * SW + 2 * 2 * 64 * SA;  // W hi/lo + A dbl-buf
constexpr int SMEM_P_BYTES = SMEM_P_ELEMS * 2;               // 152576

__device__ __forceinline__ void mma_bf16(float* c, const uint32_t* a, const uint32_t* b) {
    asm volatile(
        "mma.sync.aligned.m16n8k16.row.col.f32.bf16.bf16.f32 "
        "{%0,%1,%2,%3}, {%4,%5,%6,%7}, {%8,%9}, {%0,%1,%2,%3};\n"
        : "+f"(c[0]), "+f"(c[1]), "+f"(c[2]), "+f"(c[3])
        : "r"(a[0]), "r"(a[1]), "r"(a[2]), "r"(a[3]), "r"(b[0]), "r"(b[1]));
}

__device__ __forceinline__ void cpasync16(void* smem, const void* gmem) {
    uint32_t s = (uint32_t)__cvta_generic_to_shared(smem);
    asm volatile("cp.async.ca.shared.global [%0], [%1], 16;\n" :: "r"(s), "l"(gmem));
}
__device__ __forceinline__ void cp_commit() {
    asm volatile("cp.async.commit_group;\n" ::: "memory");
}
template <int N>
__device__ __forceinline__ void cp_wait() {
    asm volatile("cp.async.wait_group %0;\n" :: "n"(N) : "memory");
}

// 3-term split-bf16 accumulation over one 64x64x32 smem tile (used by P/Y GEMMs)
__device__ __forceinline__ void compute_tile(
    const __nv_bfloat16* sAhi, const __nv_bfloat16* sAlo,
    const __nv_bfloat16* sBhi, const __nv_bfloat16* sBlo,
    float acc[2][4][4], int wm, int wn, int g, int tg)
{
#pragma unroll
    for (int ks = 0; ks < 32; ks += 16) {
        uint32_t ahi[2][4], alo[2][4], bhi[4][2], blo[4][2];
#pragma unroll
        for (int mf = 0; mf < 2; mf++) {
            int off = (wm + mf * 16 + g) * SA + ks + tg * 2;
            ahi[mf][0] = *(const uint32_t*)(sAhi + off);
            ahi[mf][1] = *(const uint32_t*)(sAhi + off + 8 * SA);
            ahi[mf][2] = *(const uint32_t*)(sAhi + off + 8);
            ahi[mf][3] = *(const uint32_t*)(sAhi + off + 8 * SA + 8);
            alo[mf][0] = *(const uint32_t*)(sAlo + off);
            alo[mf][1] = *(const uint32_t*)(sAlo + off + 8 * SA);
            alo[mf][2] = *(const uint32_t*)(sAlo + off + 8);
            alo[mf][3] = *(const uint32_t*)(sAlo + off + 8 * SA + 8);
        }
#pragma unroll
        for (int nf = 0; nf < 4; nf++) {
            int off = (wn + nf * 8 + g) * SA + ks + tg * 2;
            bhi[nf][0] = *(const uint32_t*)(sBhi + off);
            bhi[nf][1] = *(const uint32_t*)(sBhi + off + 8);
            blo[nf][0] = *(const uint32_t*)(sBlo + off);
            blo[nf][1] = *(const uint32_t*)(sBlo + off + 8);
        }
#pragma unroll
        for (int mf = 0; mf < 2; mf++)
#pragma unroll
            for (int nf = 0; nf < 4; nf++) {
                mma_bf16(acc[mf][nf], ahi[mf], bhi[nf]);
                mma_bf16(acc[mf][nf], ahi[mf], blo[nf]);
                mma_bf16(acc[mf][nf], alo[mf], bhi[nf]);
            }
    }
}

// 32x16 warp tile against the resident W slab (persistent kernel)
__device__ __forceinline__ void compute_tile_p(
    const __nv_bfloat16* sAhi, const __nv_bfloat16* sAlo,
    const __nv_bfloat16* sWhi, const __nv_bfloat16* sWlo,
    float acc[2][2][4], int wm, int wn, int g, int tg, int k0)
{
#pragma unroll
    for (int ks = 0; ks < 32; ks += 16) {
        uint32_t ahi[2][4], alo[2][4], bhi[2][2], blo[2][2];
#pragma unroll
        for (int mf = 0; mf < 2; mf++) {
            int off = (wm + mf * 16 + g) * SA + ks + tg * 2;
            ahi[mf][0] = *(const uint32_t*)(sAhi + off);
            ahi[mf][1] = *(const uint32_t*)(sAhi + off + 8 * SA);
            ahi[mf][2] = *(const uint32_t*)(sAhi + off + 8);
            ahi[mf][3] = *(const uint32_t*)(sAhi + off + 8 * SA + 8);
            alo[mf][0] = *(const uint32_t*)(sAlo + off);
            alo[mf][1] = *(const uint32_t*)(sAlo + off + 8 * SA);
            alo[mf][2] = *(const uint32_t*)(sAlo + off + 8);
            alo[mf][3] = *(const uint32_t*)(sAlo + off + 8 * SA + 8);
        }
#pragma unroll
        for (int nf = 0; nf < 2; nf++) {
            int off = (wn + nf * 8 + g) * SW + k0 + ks + tg * 2;
            bhi[nf][0] = *(const uint32_t*)(sWhi + off);
            bhi[nf][1] = *(const uint32_t*)(sWhi + off + 8);
            blo[nf][0] = *(const uint32_t*)(sWlo + off);
            blo[nf][1] = *(const uint32_t*)(sWlo + off + 8);
        }
#pragma unroll
        for (int mf = 0; mf < 2; mf++)
#pragma unroll
            for (int nf = 0; nf < 2; nf++) {
                mma_bf16(acc[mf][nf], ahi[mf], bhi[nf]);
                mma_bf16(acc[mf][nf], ahi[mf], blo[nf]);
                mma_bf16(acc[mf][nf], alo[mf], bhi[nf]);
            }
    }
}

// Load a 64x32 bf16 A tile (row-major, lda elems) into padded smem.
__device__ __forceinline__ void load_A_bf16(
    __nv_bfloat16* sA, const __nv_bfloat16* g, int lda, int tid)
{
#pragma unroll
    for (int i = 0; i < 8; i++) {
        int idx = i * 128 + tid;
        int r = idx >> 4, c2 = idx & 15;
        *(uint32_t*)(sA + r * SA + c2 * 2) =
            *(const uint32_t*)(g + (size_t)r * lda + c2 * 2);
    }
}

// Load a 32x64 weight tile [k][n] (row-major), transposed into smem as [n][k].
__device__ __forceinline__ void load_B(
    __nv_bfloat16* sB, const __nv_bfloat16* g, int ldb, int tid)
{
#pragma unroll
    for (int i = 0; i < 16; i++) {
        int idx = i * 128 + tid;
        int k = idx >> 6, n = idx & 63;
        sB[n * SA + k] = g[(size_t)k * ldb + n];
    }
}

// ---------------- kernel 1: P = split(X) @ split(W_xh), out [t][b][h] -----
__global__ __launch_bounds__(128) void gemm_P_kernel(const float* __restrict__ X)
{
    __shared__ __align__(16) __nv_bfloat16 sAhi[64 * SA], sAlo[64 * SA];
    __shared__ __align__(16) __nv_bfloat16 sBhi[64 * SA], sBlo[64 * SA];
    int tid = threadIdx.x;
    int lane = tid & 31, warp = tid >> 5;
    int g = lane >> 2, tg = lane & 3;
    int wm = (warp >> 1) * 32, wn = (warp & 1) * 32;
    int n0 = blockIdx.x * 64;
    size_t m0 = (size_t)blockIdx.y * 64;

    float acc[2][4][4];
#pragma unroll
    for (int a = 0; a < 2; a++)
#pragma unroll
        for (int b = 0; b < 4; b++)
#pragma unroll
            for (int c = 0; c < 4; c++) acc[a][b][c] = 0.f;

    for (int k0 = 0; k0 < D_; k0 += 32) {
        const float* ga = X + m0 * D_ + k0;
#pragma unroll
        for (int i = 0; i < 16; i++) {
            int idx = i * 128 + tid;
            int r = idx >> 5, c = idx & 31;
            float v = ga[(size_t)r * D_ + c];
            __nv_bfloat16 hi = __float2bfloat16(v);
            sAhi[r * SA + c] = hi;
            sAlo[r * SA + c] = __float2bfloat16(v - __bfloat162float(hi));
        }
        load_B(sBhi, g_Wxh_hi + (size_t)k0 * H_ + n0, H_, tid);
        load_B(sBlo, g_Wxh_lo + (size_t)k0 * H_ + n0, H_, tid);
        __syncthreads();
        compute_tile(sAhi, sAlo, sBhi, sBlo, acc, wm, wn, g, tg);
        __syncthreads();
    }

    // input row r = b*T + t ; write P as [t][b][h]
#pragma unroll
    for (int mf = 0; mf < 2; mf++)
#pragma unroll
        for (int nf = 0; nf < 4; nf++) {
            int c = n0 + wn + nf * 8 + tg * 2;
#pragma unroll
            for (int half = 0; half < 2; half++) {
                size_t r = m0 + wm + mf * 16 + g + half * 8;
                int tt = (int)(r & (T_ - 1));
                int bb = (int)(r >> 9);
                float* p = g_P + ((size_t)tt * B_ + bb) * H_ + c;
                p[0] = acc[mf][nf][half * 2];
                p[1] = acc[mf][nf][half * 2 + 1];
            }
        }
}

// ---------------- persistent recurrence kernel -----------------------------
// Grid: 128 CTAs = 4 m-tiles(64 batch rows) x 32 n-tiles(32 cols).
// Each CTA keeps its W_hh [1024 x 32] hi/lo slab in SMEM for all T steps.
__global__ __launch_bounds__(128, 1) void rnn_persistent_kernel()
{
    extern __shared__ __align__(16) __nv_bfloat16 smem[];
    __nv_bfloat16* sWhi = smem;                  // 32 rows (n) x SW (k)
    __nv_bfloat16* sWlo = sWhi + 32 * SW;
    __nv_bfloat16* sA   = sWlo + 32 * SW;        // [2 buf][2 plane][64*SA]

    const int tid  = threadIdx.x;
    const int lane = tid & 31, warp = tid >> 5;
    const int g = lane >> 2, tg = lane & 3;
    const int wm = (warp >> 1) * 32;             // warp m offset (2 warps)
    const int wn = (warp & 1) * 16;              // warp n offset (2 warps)
    const int m0 = (int)(blockIdx.x >> 5) * 64;  // batch tile
    const int n0 = (int)(blockIdx.x & 31) * 32;  // hidden-col tile

    // Load resident W_hh slab: sW[n][k] = W_hh[k][n0+n]
    for (int idx = tid; idx < 32 * 1024; idx += 128) {
        int n = idx & 31, k = idx >> 5;
        sWhi[n * SW + k] = g_Whh_hi[(size_t)k * H_ + n0 + n];
        sWlo[n * SW + k] = g_Whh_lo[(size_t)k * H_ + n0 + n];
    }
    __syncthreads();

    for (int t = 0; t < T_; t++) {
        const __nv_bfloat16* bHi = g_Hhi + (size_t)t * BH + (size_t)m0 * H_;
        const __nv_bfloat16* bLo = g_Hlo + (size_t)t * BH + (size_t)m0 * H_;

        float acc[2][2][4];
#pragma unroll
        for (int a = 0; a < 2; a++)
#pragma unroll
            for (int b = 0; b < 4; b++) { acc[a][0][b] = 0.f; acc[a][1][b] = 0.f; }

        // prefetch k-tile 0 into buf 0
#pragma unroll
        for (int j = 0; j < 4; j++) {
            int idx = j * 128 + tid;
            int plane = idx >> 8, r = (idx >> 2) & 63, c4 = idx & 3;
            const __nv_bfloat16* src = (plane ? bLo : bHi) + (size_t)r * H_ + c4 * 8;
            __nv_bfloat16* dst = sA + plane * (64 * SA) + r * SA + c4 * 8;
            cpasync16(dst, src);
        }
        cp_commit();

        for (int kt = 0; kt < 32; kt++) {
            int buf = kt & 1;
            if (kt < 31) {
                int nb = (kt + 1) & 1;
                int kg = (kt + 1) * 32;
#pragma unroll
                for (int j = 0; j < 4; j++) {
                    int idx = j * 128 + tid;
                    int plane = idx >> 8, r = (idx >> 2) & 63, c4 = idx & 3;
                    const __nv_bfloat16* src =
                        (plane ? bLo : bHi) + (size_t)r * H_ + kg + c4 * 8;
                    __nv_bfloat16* dst =
                        sA + nb * (2 * 64 * SA) + plane * (64 * SA) + r * SA + c4 * 8;
                    cpasync16(dst, src);
                }
                cp_commit();
                cp_wait<1>();
            } else {
                cp_wait<0>();
            }
            __syncthreads();
            compute_tile_p(sA + buf * (2 * 64 * SA),
                           sA + buf * (2 * 64 * SA) + 64 * SA,
                           sWhi, sWlo, acc, wm, wn, g, tg, kt * 32);
            __syncthreads();
        }

        // epilogue: h_next = tanh(acc + P[t]); store split into slot t+1
        const float* Pt = g_P + (size_t)t * BH;
        __nv_bfloat16* oHi = g_Hhi + (size_t)(t + 1) * BH;
        __nv_bfloat16* oLo = g_Hlo + (size_t)(t + 1) * BH;
#pragma unroll
        for (int mf = 0; mf < 2; mf++)
#pragma unroll
            for (int nf = 0; nf < 2; nf++)
#pragma unroll
                for (int half = 0; half < 2; half++) {
                    int rr = m0 + wm + mf * 16 + g + half * 8;
                    int cc = n0 + wn + nf * 8 + tg * 2;
                    float2 p = *(const float2*)(Pt + (size_t)rr * H_ + cc);
                    float h0v = tanhf(acc[mf][nf][half * 2]     + p.x);
                    float h1v = tanhf(acc[mf][nf][half * 2 + 1] + p.y);
                    __nv_bfloat16 h0h = __float2bfloat16(h0v);
                    __nv_bfloat16 h1h = __float2bfloat16(h1v);
                    __nv_bfloat162 hhi; hhi.x = h0h; hhi.y = h1h;
                    __nv_bfloat162 hlo;
                    hlo.x = __float2bfloat16(h0v - __bfloat162float(h0h));
                    hlo.y = __float2bfloat16(h1v - __bfloat162float(h1h));
                    *(__nv_bfloat162*)(oHi + (size_t)rr * H_ + cc) = hhi;
                    *(__nv_bfloat162*)(oLo + (size_t)rr * H_ + cc) = hlo;
                }

        // grid barrier (monotonic counter; reset by reset_kernel each launch)
        __threadfence();
        __syncthreads();
        if (tid == 0) {
            atomicAdd(&g_bar_count, 1u);
            unsigned target = (unsigned)NCTA_P * (unsigned)(t + 1);
            unsigned v;
            do {
                asm volatile("ld.acquire.gpu.u32 %0, [%1];"
                             : "=r"(v) : "l"(&g_bar_count));
                if (v >= target) break;
                __nanosleep(64);
            } while (true);
        }
        __syncthreads();
    }
}

// ---------------- kernel 3: Y = H_all @ W_hy ------------------------------
__global__ __launch_bounds__(128) void gemm_Y_kernel(float* __restrict__ out)
{
    __shared__ __align__(16) __nv_bfloat16 sAhi[64 * SA], sAlo[64 * SA];
    __shared__ __align__(16) __nv_bfloat16 sBhi[64 * SA], sBlo[64 * SA];
    int tid = threadIdx.x;
    int lane = tid & 31, warp = tid >> 5;
    int g = lane >> 2, tg = lane & 3;
    int wm = (warp >> 1) * 32, wn = (warp & 1) * 32;
    int n0 = blockIdx.x * 64;
    int m0 = blockIdx.y * 64;

    float acc[2][4][4];
#pragma unroll
    for (int a = 0; a < 2; a++)
#pragma unroll
        for (int b = 0; b < 4; b++)
#pragma unroll
            for (int c = 0; c < 4; c++) acc[a][b][c] = 0.f;

    for (int k0 = 0; k0 < H_; k0 += 32) {
#pragma unroll
        for (int i = 0; i < 8; i++) {
            int idx = i * 128 + tid;
            int r = idx >> 4, c2 = idx & 15;
            int m = m0 + r;
            int tt = m & (T_ - 1);
            int bb = m >> 9;
            size_t base = (size_t)(tt + 1) * BH + (size_t)bb * H_ + k0 + c2 * 2;
            *(uint32_t*)(sAhi + r * SA + c2 * 2) = *(const uint32_t*)(g_Hhi + base);
            *(uint32_t*)(sAlo + r * SA + c2 * 2) = *(const uint32_t*)(g_Hlo + base);
        }
        load_B(sBhi, g_Why_hi + (size_t)k0 * O_ + n0, O_, tid);
        load_B(sBlo, g_Why_lo + (size_t)k0 * O_ + n0, O_, tid);
        __syncthreads();
        compute_tile(sAhi, sAlo, sBhi, sBlo, acc, wm, wn, g, tg);
        __syncthreads();
    }

#pragma unroll
    for (int mf = 0; mf < 2; mf++)
#pragma unroll
        for (int nf = 0; nf < 4; nf++) {
            size_t r = (size_t)m0 + wm + mf * 16 + g;
            int c = n0 + wn + nf * 8 + tg * 2;
            out[r * O_ + c]           = acc[mf][nf][0];
            out[r * O_ + c + 1]       = acc[mf][nf][1];
            out[(r + 8) * O_ + c]     = acc[mf][nf][2];
            out[(r + 8) * O_ + c + 1] = acc[mf][nf][3];
        }
}

// ---------------- small utility kernels -----------------------------------
__global__ void split_f32_kernel(const float* __restrict__ src,
                                 __nv_bfloat16* __restrict__ hi,
                                 __nv_bfloat16* __restrict__ lo, int n)
{
    int i = blockIdx.x * 256 + threadIdx.x;
    if (i < n) {
        float v = src[i];
        __nv_bfloat16 h = __float2bfloat16(v);
        hi[i] = h;
        lo[i] = __float2bfloat16(v - __bfloat162float(h));
    }
}

__global__ void reset_kernel()
{
    if (threadIdx.x == 0) g_bar_count = 0;
}

__global__ void final_h_kernel(float* __restrict__ out)
{
    int i = blockIdx.x * 256 + threadIdx.x;
    if (i < BH) {
        size_t o = (size_t)T_ * BH + i;
        out[BTO + i] = __bfloat162float(g_Hhi[o]) + __bfloat162float(g_Hlo[o]);
    }
}

// ---------------- launch ---------------------------------------------------
extern "C" void kernel_launch(void* const* d_in, const int* in_sizes, int n_in,
                              void* d_out, int out_size)
{
    (void)in_sizes; (void)n_in; (void)out_size;
    const float* x    = (const float*)d_in[0];
    const float* h0   = (const float*)d_in[1];
    const float* w_xh = (const float*)d_in[2];
    const float* w_hh = (const float*)d_in[3];
    const float* w_hy = (const float*)d_in[4];
    float* out = (float*)d_out;

    __nv_bfloat16 *p_Wxh_hi, *p_Wxh_lo, *p_Whh_hi, *p_Whh_lo,
                  *p_Why_hi, *p_Why_lo, *p_Hhi, *p_Hlo;
    cudaGetSymbolAddress((void**)&p_Wxh_hi, g_Wxh_hi);
    cudaGetSymbolAddress((void**)&p_Wxh_lo, g_Wxh_lo);
    cudaGetSymbolAddress((void**)&p_Whh_hi, g_Whh_hi);
    cudaGetSymbolAddress((void**)&p_Whh_lo, g_Whh_lo);
    cudaGetSymbolAddress((void**)&p_Why_hi, g_Why_hi);
    cudaGetSymbolAddress((void**)&p_Why_lo, g_Why_lo);
    cudaGetSymbolAddress((void**)&p_Hhi,    g_Hhi);
    cudaGetSymbolAddress((void**)&p_Hlo,    g_Hlo);

    cudaFuncSetAttribute(rnn_persistent_kernel,
                         cudaFuncAttributeMaxDynamicSharedMemorySize, SMEM_P_BYTES);

    // Split weights and h0 (slot 0 of the h ring); reset grid barrier.
    reset_kernel<<<1, 32>>>();
    split_f32_kernel<<<(D_ * H_ + 255) / 256, 256>>>(w_xh, p_Wxh_hi, p_Wxh_lo, D_ * H_);
    split_f32_kernel<<<(H_ * H_ + 255) / 256, 256>>>(w_hh, p_Whh_hi, p_Whh_lo, H_ * H_);
    split_f32_kernel<<<(H_ * O_ + 255) / 256, 256>>>(w_hy, p_Why_hi, p_Why_lo, H_ * O_);
    split_f32_kernel<<<(BH + 255) / 256, 256>>>(h0, p_Hhi, p_Hlo, BH);

    // Phase 1: P = X @ W_xh for all timesteps (parallel), layout [t][b][h].
    gemm_P_kernel<<<dim3(H_ / 64, (B_ * T_) / 64), 128>>>(x);

    // Phase 2: whole recurrence in ONE persistent kernel (grid barrier inside).
    rnn_persistent_kernel<<<NCTA_P, 128, SMEM_P_BYTES>>>();

    // Phase 3: Y = H_all @ W_hy (parallel), plus final h.
    gemm_Y_kernel<<<dim3(O_ / 64, (B_ * T_) / 64), 128>>>(out);
    final_h_kernel<<<(BH + 255) / 256, 256>>>(out);
}

// round 3
// speedup vs baseline: 2.9915x; 1.3477x over previous
#include <cuda_runtime.h>
#include <cuda_bf16.h>
#include <cstdint>
#include <cstddef>

// Problem dims
#define B_ 256
#define T_ 512
#define D_ 512
#define H_ 1024
#define O_ 512

constexpr int    BH  = B_ * H_;                      // 262144
constexpr size_t BTH = (size_t)B_ * T_ * H_;         // 134217728
constexpr size_t BTO = (size_t)B_ * T_ * O_;         // 67108864

// ---------------- scratch (static __device__ arrays; no runtime alloc) ----
__device__ float         g_P[BTH];                           // x @ W_xh, fp32, [t][b][h]
__device__ __nv_bfloat16 g_Hhi[(size_t)(T_ + 1) * BH];       // split h, hi plane
__device__ __nv_bfloat16 g_Hlo[(size_t)(T_ + 1) * BH];       // split h, lo plane
__device__ __nv_bfloat16 g_Wxh_hi[D_ * H_], g_Wxh_lo[D_ * H_];
__device__ __nv_bfloat16 g_Whh_hi[H_ * H_], g_Whh_lo[H_ * H_];
__device__ __nv_bfloat16 g_Why_hi[H_ * O_], g_Why_lo[H_ * O_];
__device__ unsigned      g_bar[4 * 32];                      // 4 group barriers, 128B apart

// ---------------- tile geometry -------------------------------------------
constexpr int SA   = 40;    // padded smem row stride for 32-k tiles (P/Y)
constexpr int SA_R = 136;   // padded row stride for 128-k A tiles (step)
constexpr int SW   = 1032;  // padded row stride for resident W slab (k dim)
constexpr int KT   = 128;   // step-kernel k-tile
constexpr int NKT  = H_ / KT;  // 8

constexpr int NCTA_P = 128;
constexpr int SMEM_P_ELEMS = 2 * 32 * SW + 2 * 2 * 64 * SA_R;
constexpr int SMEM_P_BYTES = SMEM_P_ELEMS * 2;   // 201728

__device__ __forceinline__ void mma_bf16(float* c, const uint32_t* a, const uint32_t* b) {
    asm volatile(
        "mma.sync.aligned.m16n8k16.row.col.f32.bf16.bf16.f32 "
        "{%0,%1,%2,%3}, {%4,%5,%6,%7}, {%8,%9}, {%0,%1,%2,%3};\n"
        : "+f"(c[0]), "+f"(c[1]), "+f"(c[2]), "+f"(c[3])
        : "r"(a[0]), "r"(a[1]), "r"(a[2]), "r"(a[3]), "r"(b[0]), "r"(b[1]));
}

__device__ __forceinline__ void cpasync16(void* smem, const void* gmem) {
    uint32_t s = (uint32_t)__cvta_generic_to_shared(smem);
    asm volatile("cp.async.ca.shared.global [%0], [%1], 16;\n" :: "r"(s), "l"(gmem));
}
__device__ __forceinline__ void cp_commit() {
    asm volatile("cp.async.commit_group;\n" ::: "memory");
}
template <int N>
__device__ __forceinline__ void cp_wait() {
    asm volatile("cp.async.wait_group %0;\n" :: "n"(N) : "memory");
}

// 3-term split-bf16 accumulation over one 64x64x32 smem tile (P/Y GEMMs)
__device__ __forceinline__ void compute_tile(
    const __nv_bfloat16* sAhi, const __nv_bfloat16* sAlo,
    const __nv_bfloat16* sBhi, const __nv_bfloat16* sBlo,
    float acc[2][4][4], int wm, int wn, int g, int tg)
{
#pragma unroll
    for (int ks = 0; ks < 32; ks += 16) {
        uint32_t ahi[2][4], alo[2][4], bhi[4][2], blo[4][2];
#pragma unroll
        for (int mf = 0; mf < 2; mf++) {
            int off = (wm + mf * 16 + g) * SA + ks + tg * 2;
            ahi[mf][0] = *(const uint32_t*)(sAhi + off);
            ahi[mf][1] = *(const uint32_t*)(sAhi + off + 8 * SA);
            ahi[mf][2] = *(const uint32_t*)(sAhi + off + 8);
            ahi[mf][3] = *(const uint32_t*)(sAhi + off + 8 * SA + 8);
            alo[mf][0] = *(const uint32_t*)(sAlo + off);
            alo[mf][1] = *(const uint32_t*)(sAlo + off + 8 * SA);
            alo[mf][2] = *(const uint32_t*)(sAlo + off + 8);
            alo[mf][3] = *(const uint32_t*)(sAlo + off + 8 * SA + 8);
        }
#pragma unroll
        for (int nf = 0; nf < 4; nf++) {
            int off = (wn + nf * 8 + g) * SA + ks + tg * 2;
            bhi[nf][0] = *(const uint32_t*)(sBhi + off);
            bhi[nf][1] = *(const uint32_t*)(sBhi + off + 8);
            blo[nf][0] = *(const uint32_t*)(sBlo + off);
            blo[nf][1] = *(const uint32_t*)(sBlo + off + 8);
        }
#pragma unroll
        for (int mf = 0; mf < 2; mf++)
#pragma unroll
            for (int nf = 0; nf < 4; nf++) {
                mma_bf16(acc[mf][nf], ahi[mf], bhi[nf]);
                mma_bf16(acc[mf][nf], ahi[mf], blo[nf]);
                mma_bf16(acc[mf][nf], alo[mf], bhi[nf]);
            }
    }
}

// Load a 32x64 weight tile [k][n] (row-major), transposed into smem as [n][k].
__device__ __forceinline__ void load_B(
    __nv_bfloat16* sB, const __nv_bfloat16* g, int ldb, int tid)
{
#pragma unroll
    for (int i = 0; i < 16; i++) {
        int idx = i * 128 + tid;
        int k = idx >> 6, n = idx & 63;
        sB[n * SA + k] = g[(size_t)k * ldb + n];
    }
}

// ---------------- kernel 1: P = split(X) @ split(W_xh), out [t][b][h] -----
__global__ __launch_bounds__(128) void gemm_P_kernel(const float* __restrict__ X)
{
    __shared__ __align__(16) __nv_bfloat16 sAhi[64 * SA], sAlo[64 * SA];
    __shared__ __align__(16) __nv_bfloat16 sBhi[64 * SA], sBlo[64 * SA];
    int tid = threadIdx.x;
    int lane = tid & 31, warp = tid >> 5;
    int g = lane >> 2, tg = lane & 3;
    int wm = (warp >> 1) * 32, wn = (warp & 1) * 32;
    int n0 = blockIdx.x * 64;
    size_t m0 = (size_t)blockIdx.y * 64;

    float acc[2][4][4];
#pragma unroll
    for (int a = 0; a < 2; a++)
#pragma unroll
        for (int b = 0; b < 4; b++)
#pragma unroll
            for (int c = 0; c < 4; c++) acc[a][b][c] = 0.f;

    for (int k0 = 0; k0 < D_; k0 += 32) {
        const float* ga = X + m0 * D_ + k0;
#pragma unroll
        for (int i = 0; i < 16; i++) {
            int idx = i * 128 + tid;
            int r = idx >> 5, c = idx & 31;
            float v = ga[(size_t)r * D_ + c];
            __nv_bfloat16 hi = __float2bfloat16(v);
            sAhi[r * SA + c] = hi;
            sAlo[r * SA + c] = __float2bfloat16(v - __bfloat162float(hi));
        }
        load_B(sBhi, g_Wxh_hi + (size_t)k0 * H_ + n0, H_, tid);
        load_B(sBlo, g_Wxh_lo + (size_t)k0 * H_ + n0, H_, tid);
        __syncthreads();
        compute_tile(sAhi, sAlo, sBhi, sBlo, acc, wm, wn, g, tg);
        __syncthreads();
    }

    // input row r = b*T + t ; write P as [t][b][h]
#pragma unroll
    for (int mf = 0; mf < 2; mf++)
#pragma unroll
        for (int nf = 0; nf < 4; nf++) {
            int c = n0 + wn + nf * 8 + tg * 2;
#pragma unroll
            for (int half = 0; half < 2; half++) {
                size_t r = m0 + wm + mf * 16 + g + half * 8;
                int tt = (int)(r & (T_ - 1));
                int bb = (int)(r >> 9);
                float* p = g_P + ((size_t)tt * B_ + bb) * H_ + c;
                p[0] = acc[mf][nf][half * 2];
                p[1] = acc[mf][nf][half * 2 + 1];
            }
        }
}

// ---------------- persistent recurrence kernel -----------------------------
// Grid: 128 CTAs = 4 m-groups(64 batch rows) x 32 n-tiles(32 cols).
// W_hh [1024 x 32] hi/lo resident in SMEM; K-tile 128, double-buffered cp.async;
// per-m-group grid barriers.
__global__ __launch_bounds__(128, 1) void rnn_persistent_kernel()
{
    extern __shared__ __align__(16) __nv_bfloat16 smem[];
    __nv_bfloat16* sWhi = smem;                  // 32 rows (n) x SW (k)
    __nv_bfloat16* sWlo = sWhi + 32 * SW;
    __nv_bfloat16* sA   = sWlo + 32 * SW;        // [2 buf][2 plane][64*SA_R]

    const int tid  = threadIdx.x;
    const int lane = tid & 31, warp = tid >> 5;
    const int g = lane >> 2, tg = lane & 3;
    const int wm = (warp >> 1) * 32;             // warp m offset
    const int wn = (warp & 1) * 16;              // warp n offset
    const int grp = (int)(blockIdx.x >> 5);      // batch group 0..3
    const int m0 = grp * 64;
    const int n0 = (int)(blockIdx.x & 31) * 32;

    unsigned* bar = &g_bar[grp * 32];

    // Load resident W_hh slab: sW[n][k] = W_hh[k][n0+n]
    for (int idx = tid; idx < 32 * 1024; idx += 128) {
        int n = idx & 31, k = idx >> 5;
        sWhi[n * SW + k] = g_Whh_hi[(size_t)k * H_ + n0 + n];
        sWlo[n * SW + k] = g_Whh_lo[(size_t)k * H_ + n0 + n];
    }
    __syncthreads();

    for (int t = 0; t < T_; t++) {
        const __nv_bfloat16* bHi = g_Hhi + (size_t)t * BH + (size_t)m0 * H_;
        const __nv_bfloat16* bLo = g_Hlo + (size_t)t * BH + (size_t)m0 * H_;

        // prefetch A k-tile 0 into buf 0 (2048 x 16B chunks, 16/thread)
#pragma unroll
        for (int j = 0; j < 16; j++) {
            int idx = j * 128 + tid;
            int plane = idx >> 10, rem = idx & 1023;
            int r = rem >> 4, c8 = rem & 15;
            const __nv_bfloat16* src = (plane ? bLo : bHi) + (size_t)r * H_ + c8 * 8;
            __nv_bfloat16* dst = sA + plane * (64 * SA_R) + r * SA_R + c8 * 8;
            cpasync16(dst, src);
        }
        cp_commit();

        // prefetch P[t] outputs into registers (hidden under the MMA loop)
        const float* Pt = g_P + (size_t)t * BH;
        float2 pre[2][2][2];
#pragma unroll
        for (int mf = 0; mf < 2; mf++)
#pragma unroll
            for (int nf = 0; nf < 2; nf++)
#pragma unroll
                for (int half = 0; half < 2; half++) {
                    int rr = m0 + wm + mf * 16 + g + half * 8;
                    int cc = n0 + wn + nf * 8 + tg * 2;
                    pre[mf][nf][half] = *(const float2*)(Pt + (size_t)rr * H_ + cc);
                }

        float acc[2][2][4];
#pragma unroll
        for (int a = 0; a < 2; a++)
#pragma unroll
            for (int b = 0; b < 4; b++) { acc[a][0][b] = 0.f; acc[a][1][b] = 0.f; }

        for (int kt = 0; kt < NKT; kt++) {
            int buf = kt & 1;
            if (kt < NKT - 1) {
                int nb = buf ^ 1;
                int kg = (kt + 1) * KT;
#pragma unroll
                for (int j = 0; j < 16; j++) {
                    int idx = j * 128 + tid;
                    int plane = idx >> 10, rem = idx & 1023;
                    int r = rem >> 4, c8 = rem & 15;
                    const __nv_bfloat16* src =
                        (plane ? bLo : bHi) + (size_t)r * H_ + kg + c8 * 8;
                    __nv_bfloat16* dst =
                        sA + nb * (2 * 64 * SA_R) + plane * (64 * SA_R) + r * SA_R + c8 * 8;
                    cpasync16(dst, src);
                }
                cp_commit();
                cp_wait<1>();
            } else {
                cp_wait<0>();
            }
            __syncthreads();

            const __nv_bfloat16* sAhi = sA + buf * (2 * 64 * SA_R);
            const __nv_bfloat16* sAlo = sAhi + 64 * SA_R;
            const int kW = kt * KT;
#pragma unroll
            for (int ks = 0; ks < KT; ks += 16) {
                uint32_t ahi[2][4], alo[2][4], bhi[2][2], blo[2][2];
#pragma unroll
                for (int mf = 0; mf < 2; mf++) {
                    int off = (wm + mf * 16 + g) * SA_R + ks + tg * 2;
                    ahi[mf][0] = *(const uint32_t*)(sAhi + off);
                    ahi[mf][1] = *(const uint32_t*)(sAhi + off + 8 * SA_R);
                    ahi[mf][2] = *(const uint32_t*)(sAhi + off + 8);
                    ahi[mf][3] = *(const uint32_t*)(sAhi + off + 8 * SA_R + 8);
                    alo[mf][0] = *(const uint32_t*)(sAlo + off);
                    alo[mf][1] = *(const uint32_t*)(sAlo + off + 8 * SA_R);
                    alo[mf][2] = *(const uint32_t*)(sAlo + off + 8);
                    alo[mf][3] = *(const uint32_t*)(sAlo + off + 8 * SA_R + 8);
                }
#pragma unroll
                for (int nf = 0; nf < 2; nf++) {
                    int off = (wn + nf * 8 + g) * SW + kW + ks + tg * 2;
                    bhi[nf][0] = *(const uint32_t*)(sWhi + off);
                    bhi[nf][1] = *(const uint32_t*)(sWhi + off + 8);
                    blo[nf][0] = *(const uint32_t*)(sWlo + off);
                    blo[nf][1] = *(const uint32_t*)(sWlo + off + 8);
                }
#pragma unroll
                for (int mf = 0; mf < 2; mf++)
#pragma unroll
                    for (int nf = 0; nf < 2; nf++) {
                        mma_bf16(acc[mf][nf], ahi[mf], bhi[nf]);
                        mma_bf16(acc[mf][nf], ahi[mf], blo[nf]);
                        mma_bf16(acc[mf][nf], alo[mf], bhi[nf]);
                    }
            }
            __syncthreads();
        }

        // epilogue: h_next = tanh(acc + P[t]); store split into slot t+1
        __nv_bfloat16* oHi = g_Hhi + (size_t)(t + 1) * BH;
        __nv_bfloat16* oLo = g_Hlo + (size_t)(t + 1) * BH;
#pragma unroll
        for (int mf = 0; mf < 2; mf++)
#pragma unroll
            for (int nf = 0; nf < 2; nf++)
#pragma unroll
                for (int half = 0; half < 2; half++) {
                    int rr = m0 + wm + mf * 16 + g + half * 8;
                    int cc = n0 + wn + nf * 8 + tg * 2;
                    float2 p = pre[mf][nf][half];
                    float h0v = tanhf(acc[mf][nf][half * 2]     + p.x);
                    float h1v = tanhf(acc[mf][nf][half * 2 + 1] + p.y);
                    __nv_bfloat16 h0h = __float2bfloat16(h0v);
                    __nv_bfloat16 h1h = __float2bfloat16(h1v);
                    __nv_bfloat162 hhi; hhi.x = h0h; hhi.y = h1h;
                    __nv_bfloat162 hlo;
                    hlo.x = __float2bfloat16(h0v - __bfloat162float(h0h));
                    hlo.y = __float2bfloat16(h1v - __bfloat162float(h1h));
                    *(__nv_bfloat162*)(oHi + (size_t)rr * H_ + cc) = hhi;
                    *(__nv_bfloat162*)(oLo + (size_t)rr * H_ + cc) = hlo;
                }

        // per-group grid barrier (32 CTAs sharing this batch slice)
        __threadfence();
        __syncthreads();
        if (tid == 0) {
            atomicAdd(bar, 1u);
            unsigned target = 32u * (unsigned)(t + 1);
            unsigned v;
            do {
                asm volatile("ld.acquire.gpu.u32 %0, [%1];" : "=r"(v) : "l"(bar));
                if (v >= target) break;
                __nanosleep(32);
            } while (true);
        }
        __syncthreads();
    }
}

// ---------------- kernel 3: Y = H_all @ W_hy ------------------------------
__global__ __launch_bounds__(128) void gemm_Y_kernel(float* __restrict__ out)
{
    __shared__ __align__(16) __nv_bfloat16 sAhi[64 * SA], sAlo[64 * SA];
    __shared__ __align__(16) __nv_bfloat16 sBhi[64 * SA], sBlo[64 * SA];
    int tid = threadIdx.x;
    int lane = tid & 31, warp = tid >> 5;
    int g = lane >> 2, tg = lane & 3;
    int wm = (warp >> 1) * 32, wn = (warp & 1) * 32;
    int n0 = blockIdx.x * 64;
    int m0 = blockIdx.y * 64;

    float acc[2][4][4];
#pragma unroll
    for (int a = 0; a < 2; a++)
#pragma unroll
        for (int b = 0; b < 4; b++)
#pragma unroll
            for (int c = 0; c < 4; c++) acc[a][b][c] = 0.f;

    for (int k0 = 0; k0 < H_; k0 += 32) {
#pragma unroll
        for (int i = 0; i < 8; i++) {
            int idx = i * 128 + tid;
            int r = idx >> 4, c2 = idx & 15;
            int m = m0 + r;
            int tt = m & (T_ - 1);
            int bb = m >> 9;
            size_t base = (size_t)(tt + 1) * BH + (size_t)bb * H_ + k0 + c2 * 2;
            *(uint32_t*)(sAhi + r * SA + c2 * 2) = *(const uint32_t*)(g_Hhi + base);
            *(uint32_t*)(sAlo + r * SA + c2 * 2) = *(const uint32_t*)(g_Hlo + base);
        }
        load_B(sBhi, g_Why_hi + (size_t)k0 * O_ + n0, O_, tid);
        load_B(sBlo, g_Why_lo + (size_t)k0 * O_ + n0, O_, tid);
        __syncthreads();
        compute_tile(sAhi, sAlo, sBhi, sBlo, acc, wm, wn, g, tg);
        __syncthreads();
    }

#pragma unroll
    for (int mf = 0; mf < 2; mf++)
#pragma unroll
        for (int nf = 0; nf < 4; nf++) {
            size_t r = (size_t)m0 + wm + mf * 16 + g;
            int c = n0 + wn + nf * 8 + tg * 2;
            out[r * O_ + c]           = acc[mf][nf][0];
            out[r * O_ + c + 1]       = acc[mf][nf][1];
            out[(r + 8) * O_ + c]     = acc[mf][nf][2];
            out[(r + 8) * O_ + c + 1] = acc[mf][nf][3];
        }
}

// ---------------- small utility kernels -----------------------------------
__global__ void split_f32_kernel(const float* __restrict__ src,
                                 __nv_bfloat16* __restrict__ hi,
                                 __nv_bfloat16* __restrict__ lo, int n)
{
    int i = blockIdx.x * 256 + threadIdx.x;
    if (i < n) {
        float v = src[i];
        __nv_bfloat16 h = __float2bfloat16(v);
        hi[i] = h;
        lo[i] = __float2bfloat16(v - __bfloat162float(h));
    }
}

__global__ void reset_kernel()
{
    if (threadIdx.x < 4 * 32) g_bar[threadIdx.x] = 0;
}

__global__ void final_h_kernel(float* __restrict__ out)
{
    int i = blockIdx.x * 256 + threadIdx.x;
    if (i < BH) {
        size_t o = (size_t)T_ * BH + i;
        out[BTO + i] = __bfloat162float(g_Hhi[o]) + __bfloat162float(g_Hlo[o]);
    }
}

// ---------------- launch ---------------------------------------------------
extern "C" void kernel_launch(void* const* d_in, const int* in_sizes, int n_in,
                              void* d_out, int out_size)
{
    (void)in_sizes; (void)n_in; (void)out_size;
    const float* x    = (const float*)d_in[0];
    const float* h0   = (const float*)d_in[1];
    const float* w_xh = (const float*)d_in[2];
    const float* w_hh = (const float*)d_in[3];
    const float* w_hy = (const float*)d_in[4];
    float* out = (float*)d_out;

    __nv_bfloat16 *p_Wxh_hi, *p_Wxh_lo, *p_Whh_hi, *p_Whh_lo,
                  *p_Why_hi, *p_Why_lo, *p_Hhi, *p_Hlo;
    cudaGetSymbolAddress((void**)&p_Wxh_hi, g_Wxh_hi);
    cudaGetSymbolAddress((void**)&p_Wxh_lo, g_Wxh_lo);
    cudaGetSymbolAddress((void**)&p_Whh_hi, g_Whh_hi);
    cudaGetSymbolAddress((void**)&p_Whh_lo, g_Whh_lo);
    cudaGetSymbolAddress((void**)&p_Why_hi, g_Why_hi);
    cudaGetSymbolAddress((void**)&p_Why_lo, g_Why_lo);
    cudaGetSymbolAddress((void**)&p_Hhi,    g_Hhi);
    cudaGetSymbolAddress((void**)&p_Hlo,    g_Hlo);

    cudaFuncSetAttribute(rnn_persistent_kernel,
                         cudaFuncAttributeMaxDynamicSharedMemorySize, SMEM_P_BYTES);

    // Split weights and h0 (slot 0 of the h ring); reset group barriers.
    reset_kernel<<<1, 128>>>();
    split_f32_kernel<<<(D_ * H_ + 255) / 256, 256>>>(w_xh, p_Wxh_hi, p_Wxh_lo, D_ * H_);
    split_f32_kernel<<<(H_ * H_ + 255) / 256, 256>>>(w_hh, p_Whh_hi, p_Whh_lo, H_ * H_);
    split_f32_kernel<<<(H_ * O_ + 255) / 256, 256>>>(w_hy, p_Why_hi, p_Why_lo, H_ * O_);
    split_f32_kernel<<<(BH + 255) / 256, 256>>>(h0, p_Hhi, p_Hlo, BH);

    // Phase 1: P = X @ W_xh for all timesteps (parallel), layout [t][b][h].
    gemm_P_kernel<<<dim3(H_ / 64, (B_ * T_) / 64), 128>>>(x);

    // Phase 2: whole recurrence in ONE persistent kernel (group barriers inside).
    rnn_persistent_kernel<<<NCTA_P, 128, SMEM_P_BYTES>>>();

    // Phase 3: Y = H_all @ W_hy (parallel), plus final h.
    gemm_Y_kernel<<<dim3(O_ / 64, (B_ * T_) / 64), 128>>>(out);
    final_h_kernel<<<(BH + 255) / 256, 256>>>(out);
}

// round 5
// speedup vs baseline: 3.0019x; 1.0035x over previous
#include <cuda_runtime.h>
#include <cuda_bf16.h>
#include <cstdint>
#include <cstddef>

// Problem dims
#define B_ 256
#define T_ 512
#define D_ 512
#define H_ 1024
#define O_ 512

constexpr int    BH  = B_ * H_;                      // 262144
constexpr size_t BTH = (size_t)B_ * T_ * H_;         // 134217728
constexpr size_t BTO = (size_t)B_ * T_ * O_;         // 67108864

// ---------------- scratch (static __device__ arrays; no runtime alloc) ----
__device__ float         g_P[BTH];                           // x @ W_xh, fp32, [t][b][h]
__device__ __nv_bfloat16 g_Hhi[(size_t)(T_ + 1) * BH];       // split h, hi plane
__device__ __nv_bfloat16 g_Hlo[(size_t)(T_ + 1) * BH];       // split h, lo plane
__device__ __nv_bfloat16 g_Wxh_hi[D_ * H_], g_Wxh_lo[D_ * H_];
__device__ __nv_bfloat16 g_Whh_hi[H_ * H_], g_Whh_lo[H_ * H_];
__device__ __nv_bfloat16 g_Why_hi[H_ * O_], g_Why_lo[H_ * O_];
__device__ unsigned      g_bar[4 * 32];                      // group barriers (128B apart)

// ---------------- recurrence kernel geometry ------------------------------
// 128 CTAs = 4 batch groups (64 rows) x 32 n-tiles (32 cols), 128 threads.
// W_hh hi/lo resident in SMEM [n=32][k=1024], ldmatrix-friendly padded rows.
// A (h) streamed in 16 chunks of K=64 through a 3-stage cp.async pipeline.
constexpr int SW   = 1032;                 // W slab row stride (elems) -> 2064B
constexpr int SA_R = 72;                   // A tile row stride (elems) -> 144B
constexpr int KT   = 64;
constexpr int NKT  = H_ / KT;              // 16

constexpr int SM_WHI   = 1024;
constexpr int SM_WLO   = SM_WHI + 32 * SW * 2;      // +66048
constexpr int SM_ABASE = SM_WLO + 32 * SW * 2;      // 133120
constexpr int A_PLANE  = 64 * SA_R * 2;             // 9216 B
constexpr int A_STAGE  = 2 * A_PLANE;               // 18432 B
constexpr int SMEM_RNN = SM_ABASE + 3 * A_STAGE;    // 188416 B

// ---------------- PTX helpers ---------------------------------------------
__device__ __forceinline__ void mma_bf16(float* c, const uint32_t* a, const uint32_t* b) {
    asm volatile(
        "mma.sync.aligned.m16n8k16.row.col.f32.bf16.bf16.f32 "
        "{%0,%1,%2,%3}, {%4,%5,%6,%7}, {%8,%9}, {%0,%1,%2,%3};\n"
        : "+f"(c[0]), "+f"(c[1]), "+f"(c[2]), "+f"(c[3])
        : "r"(a[0]), "r"(a[1]), "r"(a[2]), "r"(a[3]), "r"(b[0]), "r"(b[1]));
}
__device__ __forceinline__ void ldsm_x4(uint32_t* r, uint32_t saddr) {
    asm volatile("ldmatrix.sync.aligned.m8n8.x4.shared.b16 {%0,%1,%2,%3}, [%4];"
                 : "=r"(r[0]), "=r"(r[1]), "=r"(r[2]), "=r"(r[3]) : "r"(saddr));
}
__device__ __forceinline__ void cpasync16(uint32_t smem_addr, const void* gmem) {
    asm volatile("cp.async.ca.shared.global [%0], [%1], 16;\n"
                 :: "r"(smem_addr), "l"(gmem));
}
__device__ __forceinline__ void cp_commit() {
    asm volatile("cp.async.commit_group;\n" ::: "memory");
}
template <int N>
__device__ __forceinline__ void cp_wait() {
    asm volatile("cp.async.wait_group %0;\n" :: "n"(N) : "memory");
}

// ---------------- mma.sync machinery for P / Y GEMMs ----------------------
constexpr int SA = 40;

__device__ __forceinline__ void compute_tile(
    const __nv_bfloat16* sAhi, const __nv_bfloat16* sAlo,
    const __nv_bfloat16* sBhi, const __nv_bfloat16* sBlo,
    float acc[2][4][4], int wm, int wn, int g, int tg)
{
#pragma unroll
    for (int ks = 0; ks < 32; ks += 16) {
        uint32_t ahi[2][4], alo[2][4], bhi[4][2], blo[4][2];
#pragma unroll
        for (int mf = 0; mf < 2; mf++) {
            int off = (wm + mf * 16 + g) * SA + ks + tg * 2;
            ahi[mf][0] = *(const uint32_t*)(sAhi + off);
            ahi[mf][1] = *(const uint32_t*)(sAhi + off + 8 * SA);
            ahi[mf][2] = *(const uint32_t*)(sAhi + off + 8);
            ahi[mf][3] = *(const uint32_t*)(sAhi + off + 8 * SA + 8);
            alo[mf][0] = *(const uint32_t*)(sAlo + off);
            alo[mf][1] = *(const uint32_t*)(sAlo + off + 8 * SA);
            alo[mf][2] = *(const uint32_t*)(sAlo + off + 8);
            alo[mf][3] = *(const uint32_t*)(sAlo + off + 8 * SA + 8);
        }
#pragma unroll
        for (int nf = 0; nf < 4; nf++) {
            int off = (wn + nf * 8 + g) * SA + ks + tg * 2;
            bhi[nf][0] = *(const uint32_t*)(sBhi + off);
            bhi[nf][1] = *(const uint32_t*)(sBhi + off + 8);
            blo[nf][0] = *(const uint32_t*)(sBlo + off);
            blo[nf][1] = *(const uint32_t*)(sBlo + off + 8);
        }
#pragma unroll
        for (int mf = 0; mf < 2; mf++)
#pragma unroll
            for (int nf = 0; nf < 4; nf++) {
                mma_bf16(acc[mf][nf], ahi[mf], bhi[nf]);
                mma_bf16(acc[mf][nf], ahi[mf], blo[nf]);
                mma_bf16(acc[mf][nf], alo[mf], bhi[nf]);
            }
    }
}

__device__ __forceinline__ void load_B(
    __nv_bfloat16* sB, const __nv_bfloat16* g, int ldb, int tid)
{
#pragma unroll
    for (int i = 0; i < 16; i++) {
        int idx = i * 128 + tid;
        int k = idx >> 6, n = idx & 63;
        sB[n * SA + k] = g[(size_t)k * ldb + n];
    }
}

// ---------------- kernel: P = split(X) @ split(W_xh), out [t][b][h] -------
__global__ __launch_bounds__(128) void gemm_P_kernel(const float* __restrict__ X)
{
    __shared__ __align__(16) __nv_bfloat16 sAhi[64 * SA], sAlo[64 * SA];
    __shared__ __align__(16) __nv_bfloat16 sBhi[64 * SA], sBlo[64 * SA];
    int tid = threadIdx.x;
    int lane = tid & 31, warp = tid >> 5;
    int g = lane >> 2, tg = lane & 3;
    int wm = (warp >> 1) * 32, wn = (warp & 1) * 32;
    int n0 = blockIdx.x * 64;
    size_t m0 = (size_t)blockIdx.y * 64;

    float acc[2][4][4];
#pragma unroll
    for (int a = 0; a < 2; a++)
#pragma unroll
        for (int b = 0; b < 4; b++)
#pragma unroll
            for (int c = 0; c < 4; c++) acc[a][b][c] = 0.f;

    for (int k0 = 0; k0 < D_; k0 += 32) {
        const float* ga = X + m0 * D_ + k0;
#pragma unroll
        for (int i = 0; i < 16; i++) {
            int idx = i * 128 + tid;
            int r = idx >> 5, c = idx & 31;
            float v = ga[(size_t)r * D_ + c];
            __nv_bfloat16 hi = __float2bfloat16(v);
            sAhi[r * SA + c] = hi;
            sAlo[r * SA + c] = __float2bfloat16(v - __bfloat162float(hi));
        }
        load_B(sBhi, g_Wxh_hi + (size_t)k0 * H_ + n0, H_, tid);
        load_B(sBlo, g_Wxh_lo + (size_t)k0 * H_ + n0, H_, tid);
        __syncthreads();
        compute_tile(sAhi, sAlo, sBhi, sBlo, acc, wm, wn, g, tg);
        __syncthreads();
    }

#pragma unroll
    for (int mf = 0; mf < 2; mf++)
#pragma unroll
        for (int nf = 0; nf < 4; nf++) {
            int c = n0 + wn + nf * 8 + tg * 2;
#pragma unroll
            for (int half = 0; half < 2; half++) {
                size_t r = m0 + wm + mf * 16 + g + half * 8;
                int tt = (int)(r & (T_ - 1));
                int bb = (int)(r >> 9);
                float* p = g_P + ((size_t)tt * B_ + bb) * H_ + c;
                p[0] = acc[mf][nf][half * 2];
                p[1] = acc[mf][nf][half * 2 + 1];
            }
        }
}

// ---------------- persistent recurrence kernel (ldmatrix + HMMA) ----------
__global__ __launch_bounds__(128, 1) void rnn_persistent_kernel()
{
    extern __shared__ __align__(1024) char smem[];
    uint32_t sb = (uint32_t)__cvta_generic_to_shared(smem);

    const int tid  = threadIdx.x;
    const int lane = tid & 31, warp = tid >> 5;
    const int g  = lane >> 2, tg = lane & 3;
    const int wm = (warp >> 1) * 32;             // warp m offset (2 positions)
    const int wn = (warp & 1) * 16;              // warp n offset (2 positions)
    const int grp = (int)(blockIdx.x >> 5);      // batch group 0..3
    const int m0 = grp * 64;
    const int n0 = (int)(blockIdx.x & 31) * 32;
    unsigned* bar = &g_bar[grp * 32];

    // Resident W_hh slabs: sW[n][k] = W_hh[k][n0+n], padded stride SW.
    __nv_bfloat16* sWhi = (__nv_bfloat16*)(smem + SM_WHI);
    __nv_bfloat16* sWlo = (__nv_bfloat16*)(smem + SM_WLO);
    for (int idx = tid; idx < 32 * 1024; idx += 128) {
        int n = idx & 31, k = idx >> 5;
        sWhi[n * SW + k] = g_Whh_hi[(size_t)k * H_ + n0 + n];
        sWlo[n * SW + k] = g_Whh_lo[(size_t)k * H_ + n0 + n];
    }
    __syncthreads();

    // ldmatrix per-lane address offsets (bytes)
    // A x4: mats = {m0-7 k0, m8-15 k0, m0-7 k8, m8-15 k8}
    const int a_row  = wm + ((lane >> 3) & 1) * 8 + (lane & 7);
    const int a_koff = (lane >> 4) * 8;
    const uint32_t aoff = (uint32_t)(a_row * SA_R + a_koff) * 2;
    // B x4: mats = {n0-7 k0, n0-7 k8, n8-15 k0, n8-15 k8}
    const int b_n    = wn + (lane >> 4) * 8 + (lane & 7);
    const int b_koff = ((lane >> 3) & 1) * 8;
    const uint32_t bW = sb + SM_WHI + (uint32_t)(b_n * SW + b_koff) * 2;

    for (int t = 0; t < T_; t++) {
        const __nv_bfloat16* bHi = g_Hhi + (size_t)t * BH + (size_t)m0 * H_;
        const __nv_bfloat16* bLo = g_Hlo + (size_t)t * BH + (size_t)m0 * H_;

        // prefetch P[t] for this thread's 16 outputs (hidden under MMA loop)
        const float* Pt = g_P + (size_t)t * BH;
        float2 pre[2][2][2];
#pragma unroll
        for (int mf = 0; mf < 2; mf++)
#pragma unroll
            for (int nf = 0; nf < 2; nf++)
#pragma unroll
                for (int half = 0; half < 2; half++) {
                    int rr = m0 + wm + mf * 16 + g + half * 8;
                    int cc = n0 + wn + nf * 8 + tg * 2;
                    pre[mf][nf][half] = *(const float2*)(Pt + (size_t)rr * H_ + cc);
                }

        // 3 accumulator banks (hi*hi, hi*lo, lo*hi) -> 12 independent chains
        float acc[3][2][2][4];
#pragma unroll
        for (int q = 0; q < 3; q++)
#pragma unroll
            for (int a = 0; a < 2; a++)
#pragma unroll
                for (int b = 0; b < 2; b++)
#pragma unroll
                    for (int c = 0; c < 4; c++) acc[q][a][b][c] = 0.f;

        // ---- prologue: stage 0 and 1 loads ----
#pragma unroll
        for (int pk = 0; pk < 2; pk++) {
#pragma unroll
            for (int j = 0; j < 8; j++) {
                int idx = j * 128 + tid;
                int plane = idx >> 9, rem = idx & 511;
                int r = rem >> 3, q8 = rem & 7;
                const __nv_bfloat16* src =
                    (plane ? bLo : bHi) + (size_t)r * H_ + pk * KT + q8 * 8;
                cpasync16(sb + SM_ABASE + pk * A_STAGE + plane * A_PLANE +
                          (uint32_t)(r * SA_R + q8 * 8) * 2, src);
            }
            cp_commit();
        }

        for (int kt = 0; kt < NKT; kt++) {
            int s = kt % 3;
            if (kt == NKT - 1) cp_wait<0>(); else cp_wait<1>();
            __syncthreads();

            if (kt + 2 < NKT) {
                int s2 = (kt + 2) % 3;
#pragma unroll
                for (int j = 0; j < 8; j++) {
                    int idx = j * 128 + tid;
                    int plane = idx >> 9, rem = idx & 511;
                    int r = rem >> 3, q8 = rem & 7;
                    const __nv_bfloat16* src =
                        (plane ? bLo : bHi) + (size_t)r * H_ + (kt + 2) * KT + q8 * 8;
                    cpasync16(sb + SM_ABASE + s2 * A_STAGE + plane * A_PLANE +
                              (uint32_t)(r * SA_R + q8 * 8) * 2, src);
                }
                cp_commit();
            }

            // ---- compute chunk kt from stage s ----
            uint32_t aHi = sb + SM_ABASE + s * A_STAGE + aoff;
            uint32_t aLo = aHi + A_PLANE;
            uint32_t bHiA = bW + (uint32_t)(kt * KT) * 2;
            uint32_t bLoA = bHiA + (uint32_t)(SM_WLO - SM_WHI);
#pragma unroll
            for (int ks = 0; ks < KT; ks += 16) {
                uint32_t ah0[4], ah1[4], al0[4], al1[4], bh[4], bl[4];
                ldsm_x4(ah0, aHi + ks * 2);
                ldsm_x4(ah1, aHi + ks * 2 + 16 * SA_R * 2);
                ldsm_x4(al0, aLo + ks * 2);
                ldsm_x4(al1, aLo + ks * 2 + 16 * SA_R * 2);
                ldsm_x4(bh, bHiA + ks * 2);
                ldsm_x4(bl, bLoA + ks * 2);
                // bank 0: hi*hi
                mma_bf16(acc[0][0][0], ah0, bh + 0);
                mma_bf16(acc[0][0][1], ah0, bh + 2);
                mma_bf16(acc[0][1][0], ah1, bh + 0);
                mma_bf16(acc[0][1][1], ah1, bh + 2);
                // bank 1: hi*lo
                mma_bf16(acc[1][0][0], ah0, bl + 0);
                mma_bf16(acc[1][0][1], ah0, bl + 2);
                mma_bf16(acc[1][1][0], ah1, bl + 0);
                mma_bf16(acc[1][1][1], ah1, bl + 2);
                // bank 2: lo*hi
                mma_bf16(acc[2][0][0], al0, bh + 0);
                mma_bf16(acc[2][0][1], al0, bh + 2);
                mma_bf16(acc[2][1][0], al1, bh + 0);
                mma_bf16(acc[2][1][1], al1, bh + 2);
            }
        }

        // ---- epilogue: merge banks, add P, tanh, split-store ----
        __nv_bfloat16* oHi = g_Hhi + (size_t)(t + 1) * BH;
        __nv_bfloat16* oLo = g_Hlo + (size_t)(t + 1) * BH;
#pragma unroll
        for (int mf = 0; mf < 2; mf++)
#pragma unroll
            for (int nf = 0; nf < 2; nf++)
#pragma unroll
                for (int half = 0; half < 2; half++) {
                    int rr = m0 + wm + mf * 16 + g + half * 8;
                    int cc = n0 + wn + nf * 8 + tg * 2;
                    float2 p = pre[mf][nf][half];
                    float s0 = acc[0][mf][nf][half * 2] + acc[1][mf][nf][half * 2]
                             + acc[2][mf][nf][half * 2] + p.x;
                    float s1 = acc[0][mf][nf][half * 2 + 1] + acc[1][mf][nf][half * 2 + 1]
                             + acc[2][mf][nf][half * 2 + 1] + p.y;
                    float h0v = tanhf(s0);
                    float h1v = tanhf(s1);
                    __nv_bfloat16 h0h = __float2bfloat16(h0v);
                    __nv_bfloat16 h1h = __float2bfloat16(h1v);
                    __nv_bfloat162 hhi; hhi.x = h0h; hhi.y = h1h;
                    __nv_bfloat162 hlo;
                    hlo.x = __float2bfloat16(h0v - __bfloat162float(h0h));
                    hlo.y = __float2bfloat16(h1v - __bfloat162float(h1h));
                    *(__nv_bfloat162*)(oHi + (size_t)rr * H_ + cc) = hhi;
                    *(__nv_bfloat162*)(oLo + (size_t)rr * H_ + cc) = hlo;
                }

        // ---- per-group barrier (32 CTAs share this batch slice) ----
        __threadfence();
        __syncthreads();
        if (tid == 0) {
            atomicAdd(bar, 1u);
            unsigned target = 32u * (unsigned)(t + 1);
            unsigned v;
            do {
                asm volatile("ld.acquire.gpu.u32 %0, [%1];" : "=r"(v) : "l"(bar));
                if (v >= target) break;
                __nanosleep(32);
            } while (true);
        }
        __syncthreads();
    }
}

// ---------------- kernel: Y = H_all @ W_hy --------------------------------
__global__ __launch_bounds__(128) void gemm_Y_kernel(float* __restrict__ out)
{
    __shared__ __align__(16) __nv_bfloat16 sAhi[64 * SA], sAlo[64 * SA];
    __shared__ __align__(16) __nv_bfloat16 sBhi[64 * SA], sBlo[64 * SA];
    int tid = threadIdx.x;
    int lane = tid & 31, warp = tid >> 5;
    int g = lane >> 2, tg = lane & 3;
    int wm = (warp >> 1) * 32, wn = (warp & 1) * 32;
    int n0 = blockIdx.x * 64;
    int m0 = blockIdx.y * 64;

    float acc[2][4][4];
#pragma unroll
    for (int a = 0; a < 2; a++)
#pragma unroll
        for (int b = 0; b < 4; b++)
#pragma unroll
            for (int c = 0; c < 4; c++) acc[a][b][c] = 0.f;

    for (int k0 = 0; k0 < H_; k0 += 32) {
#pragma unroll
        for (int i = 0; i < 8; i++) {
            int idx = i * 128 + tid;
            int r = idx >> 4, c2 = idx & 15;
            int m = m0 + r;
            int tt = m & (T_ - 1);
            int bb = m >> 9;
            size_t base = (size_t)(tt + 1) * BH + (size_t)bb * H_ + k0 + c2 * 2;
            *(uint32_t*)(sAhi + r * SA + c2 * 2) = *(const uint32_t*)(g_Hhi + base);
            *(uint32_t*)(sAlo + r * SA + c2 * 2) = *(const uint32_t*)(g_Hlo + base);
        }
        load_B(sBhi, g_Why_hi + (size_t)k0 * O_ + n0, O_, tid);
        load_B(sBlo, g_Why_lo + (size_t)k0 * O_ + n0, O_, tid);
        __syncthreads();
        compute_tile(sAhi, sAlo, sBhi, sBlo, acc, wm, wn, g, tg);
        __syncthreads();
    }

#pragma unroll
    for (int mf = 0; mf < 2; mf++)
#pragma unroll
        for (int nf = 0; nf < 4; nf++) {
            size_t r = (size_t)m0 + wm + mf * 16 + g;
            int c = n0 + wn + nf * 8 + tg * 2;
            out[r * O_ + c]           = acc[mf][nf][0];
            out[r * O_ + c + 1]       = acc[mf][nf][1];
            out[(r + 8) * O_ + c]     = acc[mf][nf][2];
            out[(r + 8) * O_ + c + 1] = acc[mf][nf][3];
        }
}

// ---------------- small utility kernels -----------------------------------
__global__ void split_f32_kernel(const float* __restrict__ src,
                                 __nv_bfloat16* __restrict__ hi,
                                 __nv_bfloat16* __restrict__ lo, int n)
{
    int i = blockIdx.x * 256 + threadIdx.x;
    if (i < n) {
        float v = src[i];
        __nv_bfloat16 h = __float2bfloat16(v);
        hi[i] = h;
        lo[i] = __float2bfloat16(v - __bfloat162float(h));
    }
}

// h0 split + group-barrier reset fused (keeps rnn kernel at launch index 5)
__global__ void split_h0_reset_kernel(const float* __restrict__ src,
                                      __nv_bfloat16* __restrict__ hi,
                                      __nv_bfloat16* __restrict__ lo)
{
    if (blockIdx.x == 0 && threadIdx.x < 4) g_bar[threadIdx.x * 32] = 0;
    int i = blockIdx.x * 256 + threadIdx.x;
    if (i < BH) {
        float v = src[i];
        __nv_bfloat16 h = __float2bfloat16(v);
        hi[i] = h;
        lo[i] = __float2bfloat16(v - __bfloat162float(h));
    }
}

__global__ void final_h_kernel(float* __restrict__ out)
{
    int i = blockIdx.x * 256 + threadIdx.x;
    if (i < BH) {
        size_t o = (size_t)T_ * BH + i;
        out[BTO + i] = __bfloat162float(g_Hhi[o]) + __bfloat162float(g_Hlo[o]);
    }
}

// ---------------- launch ---------------------------------------------------
extern "C" void kernel_launch(void* const* d_in, const int* in_sizes, int n_in,
                              void* d_out, int out_size)
{
    (void)in_sizes; (void)n_in; (void)out_size;
    const float* x    = (const float*)d_in[0];
    const float* h0   = (const float*)d_in[1];
    const float* w_xh = (const float*)d_in[2];
    const float* w_hh = (const float*)d_in[3];
    const float* w_hy = (const float*)d_in[4];
    float* out = (float*)d_out;

    __nv_bfloat16 *p_Wxh_hi, *p_Wxh_lo, *p_Whh_hi, *p_Whh_lo,
                  *p_Why_hi, *p_Why_lo, *p_Hhi, *p_Hlo;
    cudaGetSymbolAddress((void**)&p_Wxh_hi, g_Wxh_hi);
    cudaGetSymbolAddress((void**)&p_Wxh_lo, g_Wxh_lo);
    cudaGetSymbolAddress((void**)&p_Whh_hi, g_Whh_hi);
    cudaGetSymbolAddress((void**)&p_Whh_lo, g_Whh_lo);
    cudaGetSymbolAddress((void**)&p_Why_hi, g_Why_hi);
    cudaGetSymbolAddress((void**)&p_Why_lo, g_Why_lo);
    cudaGetSymbolAddress((void**)&p_Hhi,    g_Hhi);
    cudaGetSymbolAddress((void**)&p_Hlo,    g_Hlo);

    cudaFuncSetAttribute(rnn_persistent_kernel,
                         cudaFuncAttributeMaxDynamicSharedMemorySize, SMEM_RNN);

    // launches 0-3: weight/h0 splits (h0 split also resets barriers)
    split_f32_kernel<<<(D_ * H_ + 255) / 256, 256>>>(w_xh, p_Wxh_hi, p_Wxh_lo, D_ * H_);
    split_f32_kernel<<<(H_ * H_ + 255) / 256, 256>>>(w_hh, p_Whh_hi, p_Whh_lo, H_ * H_);
    split_f32_kernel<<<(H_ * O_ + 255) / 256, 256>>>(w_hy, p_Why_hi, p_Why_lo, H_ * O_);
    split_h0_reset_kernel<<<(BH + 255) / 256, 256>>>(h0, p_Hhi, p_Hlo);

    // launch 4: P = X @ W_xh, layout [t][b][h]
    gemm_P_kernel<<<dim3(H_ / 64, (B_ * T_) / 64), 128>>>(x);

    // launch 5 (ncu -s 5 captures this): persistent recurrence
    rnn_persistent_kernel<<<128, 128, SMEM_RNN>>>();

    // launches 6-7: Y = H_all @ W_hy, final h
    gemm_Y_kernel<<<dim3(O_ / 64, (B_ * T_) / 64), 128>>>(out);
    final_h_kernel<<<(BH + 255) / 256, 256>>>(out);
}

// round 6
// speedup vs baseline: 4.5354x; 1.5109x over previous
#include <cuda_runtime.h>
#include <cuda_bf16.h>
#include <cstdint>
#include <cstddef>

// Problem dims
#define B_ 256
#define T_ 512
#define D_ 512
#define H_ 1024
#define O_ 512

constexpr int    BH  = B_ * H_;                      // 262144
constexpr size_t BTH = (size_t)B_ * T_ * H_;         // 134217728
constexpr size_t BTO = (size_t)B_ * T_ * O_;         // 67108864
constexpr size_t BTD = (size_t)B_ * T_ * D_;         // 67108864

// ---------------- scratch (static __device__ arrays; no runtime alloc) ----
__device__ float         g_P[BTH];                           // x @ W_xh, fp32, [t][b][h]
__device__ __nv_bfloat16 g_Hhi[(size_t)(T_ + 1) * BH];       // split h, hi plane
__device__ __nv_bfloat16 g_Hlo[(size_t)(T_ + 1) * BH];       // split h, lo plane
__device__ __nv_bfloat16 g_Xhi[BTD], g_Xlo[BTD];             // split x
__device__ __nv_bfloat16 g_Wxh_hi[D_ * H_], g_Wxh_lo[D_ * H_];
__device__ __nv_bfloat16 g_Whh_hi[H_ * H_], g_Whh_lo[H_ * H_];
__device__ __nv_bfloat16 g_Why_hi[H_ * O_], g_Why_lo[H_ * O_];
__device__ unsigned      g_bar[4 * 32];                      // group barriers (128B apart)

// ---------------- PTX helpers ---------------------------------------------
__device__ __forceinline__ void mma_bf16(float* c, const uint32_t* a, const uint32_t* b) {
    asm volatile(
        "mma.sync.aligned.m16n8k16.row.col.f32.bf16.bf16.f32 "
        "{%0,%1,%2,%3}, {%4,%5,%6,%7}, {%8,%9}, {%0,%1,%2,%3};\n"
        : "+f"(c[0]), "+f"(c[1]), "+f"(c[2]), "+f"(c[3])
        : "r"(a[0]), "r"(a[1]), "r"(a[2]), "r"(a[3]), "r"(b[0]), "r"(b[1]));
}
__device__ __forceinline__ void ldsm_x4(uint32_t* r, uint32_t saddr) {
    asm volatile("ldmatrix.sync.aligned.m8n8.x4.shared.b16 {%0,%1,%2,%3}, [%4];"
                 : "=r"(r[0]), "=r"(r[1]), "=r"(r[2]), "=r"(r[3]) : "r"(saddr));
}
__device__ __forceinline__ void ldsm_x4_t(uint32_t* r, uint32_t saddr) {
    asm volatile("ldmatrix.sync.aligned.m8n8.x4.trans.shared.b16 {%0,%1,%2,%3}, [%4];"
                 : "=r"(r[0]), "=r"(r[1]), "=r"(r[2]), "=r"(r[3]) : "r"(saddr));
}
__device__ __forceinline__ void cpasync16(uint32_t smem_addr, const void* gmem) {
    asm volatile("cp.async.ca.shared.global [%0], [%1], 16;\n"
                 :: "r"(smem_addr), "l"(gmem));
}
__device__ __forceinline__ void cp_commit() {
    asm volatile("cp.async.commit_group;\n" ::: "memory");
}
template <int N>
__device__ __forceinline__ void cp_wait() {
    asm volatile("cp.async.wait_group %0;\n" :: "n"(N) : "memory");
}
__device__ __forceinline__ void red_release_add(unsigned* p) {
    asm volatile("red.release.gpu.global.add.u32 [%0], 1;" :: "l"(p) : "memory");
}
__device__ __forceinline__ unsigned ld_acquire(const unsigned* p) {
    unsigned v;
    asm volatile("ld.acquire.gpu.u32 %0, [%1];" : "=r"(v) : "l"(p));
    return v;
}

// =================== big GEMM (P and Y) geometry ===========================
// CTA tile 128m x 128n, K-tile 32, 2-stage cp.async double buffer, 256 thr.
// A smem [m][k] stride 40 (non-trans ldmatrix); B smem [k][n] stride 136
// (ldmatrix.trans -> exact mma B fragment).
constexpr int SGA   = 40;
constexpr int SBN   = 136;
constexpr int GA_PL = 128 * SGA * 2;           // 10240 B per A plane
constexpr int GB_PL = 32 * SBN * 2;            // 8704 B per B plane
constexpr int G_STAGE = 2 * GA_PL + 2 * GB_PL; // 37888
constexpr int SMEM_G  = 2 * G_STAGE;           // 75776

__device__ __forceinline__ void g_loadB(uint32_t st, const __nv_bfloat16* Bhi,
                                        const __nv_bfloat16* Blo, int ldb,
                                        int n0, int k0, int tid)
{
#pragma unroll
    for (int j = 0; j < 4; j++) {
        int idx = j * 256 + tid;
        int plane = idx >> 9, rem = idx & 511;
        int k = rem >> 4, n16 = rem & 15;
        const __nv_bfloat16* src = (plane ? Blo : Bhi) + (size_t)(k0 + k) * ldb + n0 + n16 * 8;
        cpasync16(st + 2 * GA_PL + plane * GB_PL + (uint32_t)(k * SBN + n16 * 8) * 2, src);
    }
}

// compute one 128x128x32 stage; acc[2][8][4]
__device__ __forceinline__ void g_compute(uint32_t stA, uint32_t aoff, uint32_t boff,
                                          float acc[2][8][4])
{
    uint32_t stB = stA + 2 * GA_PL;
#pragma unroll
    for (int ks = 0; ks < 32; ks += 16) {
        uint32_t ah0[4], ah1[4], al0[4], al1[4];
        ldsm_x4(ah0, stA + aoff + ks * 2);
        ldsm_x4(ah1, stA + aoff + ks * 2 + 16 * SGA * 2);
        ldsm_x4(al0, stA + GA_PL + aoff + ks * 2);
        ldsm_x4(al1, stA + GA_PL + aoff + ks * 2 + 16 * SGA * 2);
#pragma unroll
        for (int hn = 0; hn < 2; hn++) {
            uint32_t bb0 = stB + boff + (uint32_t)(ks * SBN + hn * 32) * 2;
            uint32_t bh0[4], bh1[4], bl0[4], bl1[4];
            ldsm_x4_t(bh0, bb0);
            ldsm_x4_t(bh1, bb0 + 32);
            ldsm_x4_t(bl0, bb0 + GB_PL);
            ldsm_x4_t(bl1, bb0 + GB_PL + 32);
#pragma unroll
            for (int mf = 0; mf < 2; mf++) {
                const uint32_t* Ah = mf ? ah1 : ah0;
                const uint32_t* Al = mf ? al1 : al0;
                float* a0 = acc[mf][hn * 4 + 0];
                float* a1 = acc[mf][hn * 4 + 1];
                float* a2 = acc[mf][hn * 4 + 2];
                float* a3 = acc[mf][hn * 4 + 3];
                mma_bf16(a0, Ah, bh0 + 0);  mma_bf16(a1, Ah, bh0 + 2);
                mma_bf16(a2, Ah, bh1 + 0);  mma_bf16(a3, Ah, bh1 + 2);
                mma_bf16(a0, Ah, bl0 + 0);  mma_bf16(a1, Ah, bl0 + 2);
                mma_bf16(a2, Ah, bl1 + 0);  mma_bf16(a3, Ah, bl1 + 2);
                mma_bf16(a0, Al, bh0 + 0);  mma_bf16(a1, Al, bh0 + 2);
                mma_bf16(a2, Al, bh1 + 0);  mma_bf16(a3, Al, bh1 + 2);
            }
        }
    }
}

// ---------------- kernel: P = split(X) @ split(W_xh), out [t][b][h] -------
__global__ __launch_bounds__(256, 2) void gemm_P_kernel()
{
    extern __shared__ __align__(16) char gsm[];
    uint32_t sb = (uint32_t)__cvta_generic_to_shared(gsm);
    int tid = threadIdx.x, lane = tid & 31, warp = tid >> 5;
    int g = lane >> 2, tg = lane & 3;
    int wm = (warp >> 1) * 32, wn = (warp & 1) * 64;
    int n0 = blockIdx.x * 128;
    int m0 = blockIdx.y * 128;
    const int NK = D_ / 32;  // 16

    const uint32_t aoff =
        (uint32_t)((wm + ((lane >> 3) & 1) * 8 + (lane & 7)) * SGA + (lane >> 4) * 8) * 2;
    const uint32_t boff =
        (uint32_t)((((lane >> 3) & 1) * 8 + (lane & 7)) * SBN + wn + (lane >> 4) * 8) * 2;

    float acc[2][8][4];
#pragma unroll
    for (int a = 0; a < 2; a++)
#pragma unroll
        for (int b = 0; b < 8; b++)
#pragma unroll
            for (int c = 0; c < 4; c++) acc[a][b][c] = 0.f;

    // prologue: stage 0
#pragma unroll
    for (int j = 0; j < 4; j++) {
        int idx = j * 256 + tid;
        int plane = idx >> 9, rem = idx & 511;
        int r = rem >> 2, c4 = rem & 3;
        const __nv_bfloat16* src = (plane ? g_Xlo : g_Xhi) + (size_t)(m0 + r) * D_ + c4 * 8;
        cpasync16(sb + plane * GA_PL + (uint32_t)(r * SGA + c4 * 8) * 2, src);
    }
    g_loadB(sb, g_Wxh_hi, g_Wxh_lo, H_, n0, 0, tid);
    cp_commit();

    for (int kt = 0; kt < NK; kt++) {
        if (kt + 1 < NK) {
            uint32_t st = sb + ((kt + 1) & 1) * G_STAGE;
            int k0 = (kt + 1) * 32;
#pragma unroll
            for (int j = 0; j < 4; j++) {
                int idx = j * 256 + tid;
                int plane = idx >> 9, rem = idx & 511;
                int r = rem >> 2, c4 = rem & 3;
                const __nv_bfloat16* src =
                    (plane ? g_Xlo : g_Xhi) + (size_t)(m0 + r) * D_ + k0 + c4 * 8;
                cpasync16(st + plane * GA_PL + (uint32_t)(r * SGA + c4 * 8) * 2, src);
            }
            g_loadB(st, g_Wxh_hi, g_Wxh_lo, H_, n0, k0, tid);
            cp_commit();
            cp_wait<1>();
        } else {
            cp_wait<0>();
        }
        __syncthreads();
        g_compute(sb + (kt & 1) * G_STAGE, aoff, boff, acc);
        __syncthreads();
    }

    // scatter to g_P [t][b][h]
#pragma unroll
    for (int mf = 0; mf < 2; mf++)
#pragma unroll
        for (int nf = 0; nf < 8; nf++) {
            int c = n0 + wn + nf * 8 + tg * 2;
#pragma unroll
            for (int half = 0; half < 2; half++) {
                int r = m0 + wm + mf * 16 + g + half * 8;
                int tt = r & (T_ - 1);
                int bb = r >> 9;
                float2 v;
                v.x = acc[mf][nf][half * 2];
                v.y = acc[mf][nf][half * 2 + 1];
                *(float2*)(g_P + ((size_t)tt * B_ + bb) * H_ + c) = v;
            }
        }
}

// ---------------- kernel: Y = H_all @ W_hy --------------------------------
__global__ __launch_bounds__(256, 2) void gemm_Y_kernel(float* __restrict__ out)
{
    extern __shared__ __align__(16) char gsm[];
    uint32_t sb = (uint32_t)__cvta_generic_to_shared(gsm);
    int tid = threadIdx.x, lane = tid & 31, warp = tid >> 5;
    int g = lane >> 2, tg = lane & 3;
    int wm = (warp >> 1) * 32, wn = (warp & 1) * 64;
    int n0 = blockIdx.x * 128;
    int m0 = blockIdx.y * 128;
    const int NK = H_ / 32;  // 32

    const uint32_t aoff =
        (uint32_t)((wm + ((lane >> 3) & 1) * 8 + (lane & 7)) * SGA + (lane >> 4) * 8) * 2;
    const uint32_t boff =
        (uint32_t)((((lane >> 3) & 1) * 8 + (lane & 7)) * SBN + wn + (lane >> 4) * 8) * 2;

    float acc[2][8][4];
#pragma unroll
    for (int a = 0; a < 2; a++)
#pragma unroll
        for (int b = 0; b < 8; b++)
#pragma unroll
            for (int c = 0; c < 4; c++) acc[a][b][c] = 0.f;

#pragma unroll
    for (int j = 0; j < 4; j++) {
        int idx = j * 256 + tid;
        int plane = idx >> 9, rem = idx & 511;
        int r = rem >> 2, c4 = rem & 3;
        int m = m0 + r;
        int tt = m & (T_ - 1), bb = m >> 9;
        const __nv_bfloat16* src = (plane ? g_Hlo : g_Hhi) +
            (size_t)(tt + 1) * BH + (size_t)bb * H_ + c4 * 8;
        cpasync16(sb + plane * GA_PL + (uint32_t)(r * SGA + c4 * 8) * 2, src);
    }
    g_loadB(sb, g_Why_hi, g_Why_lo, O_, n0, 0, tid);
    cp_commit();

    for (int kt = 0; kt < NK; kt++) {
        if (kt + 1 < NK) {
            uint32_t st = sb + ((kt + 1) & 1) * G_STAGE;
            int k0 = (kt + 1) * 32;
#pragma unroll
            for (int j = 0; j < 4; j++) {
                int idx = j * 256 + tid;
                int plane = idx >> 9, rem = idx & 511;
                int r = rem >> 2, c4 = rem & 3;
                int m = m0 + r;
                int tt = m & (T_ - 1), bb = m >> 9;
                const __nv_bfloat16* src = (plane ? g_Hlo : g_Hhi) +
                    (size_t)(tt + 1) * BH + (size_t)bb * H_ + k0 + c4 * 8;
                cpasync16(st + plane * GA_PL + (uint32_t)(r * SGA + c4 * 8) * 2, src);
            }
            g_loadB(st, g_Why_hi, g_Why_lo, O_, n0, k0, tid);
            cp_commit();
            cp_wait<1>();
        } else {
            cp_wait<0>();
        }
        __syncthreads();
        g_compute(sb + (kt & 1) * G_STAGE, aoff, boff, acc);
        __syncthreads();
    }

#pragma unroll
    for (int mf = 0; mf < 2; mf++)
#pragma unroll
        for (int nf = 0; nf < 8; nf++) {
            int c = n0 + wn + nf * 8 + tg * 2;
#pragma unroll
            for (int half = 0; half < 2; half++) {
                size_t r = (size_t)m0 + wm + mf * 16 + g + half * 8;
                float2 v;
                v.x = acc[mf][nf][half * 2];
                v.y = acc[mf][nf][half * 2 + 1];
                *(float2*)(out + r * O_ + c) = v;
            }
        }
}

// =================== persistent recurrence kernel ==========================
// 128 CTAs = 4 groups (64 batch rows) x 32 n-tiles (32 cols), 256 threads.
// W_hh hi/lo resident; A streamed in 16 chunks of K=64, 3-stage cp.async,
// per-CTA chunk-order staggering; release-atomic group barrier.
constexpr int SW   = 1032;
constexpr int SA_R = 72;
constexpr int KT   = 64;
constexpr int NKT  = H_ / KT;              // 16
constexpr int SM_WHI   = 1024;
constexpr int SM_WLO   = SM_WHI + 32 * SW * 2;
constexpr int SM_ABASE = SM_WLO + 32 * SW * 2;      // 133120
constexpr int A_PLANE  = 64 * SA_R * 2;             // 9216
constexpr int A_STAGE  = 2 * A_PLANE;               // 18432
constexpr int SMEM_RNN = SM_ABASE + 3 * A_STAGE;    // 188416

__global__ __launch_bounds__(256, 1) void rnn_persistent_kernel()
{
    extern __shared__ __align__(1024) char smem[];
    uint32_t sb = (uint32_t)__cvta_generic_to_shared(smem);

    const int tid  = threadIdx.x;
    const int lane = tid & 31, warp = tid >> 5;
    const int g = lane >> 2, tg = lane & 3;
    const int wm = (warp & 3) * 16;              // 4 m positions (64 rows)
    const int wn = (warp >> 2) * 16;             // 2 n positions (32 cols)
    const int grp = (int)(blockIdx.x >> 5);
    const int m0 = grp * 64;
    const int n0 = (int)(blockIdx.x & 31) * 32;
    const int off = (int)(blockIdx.x & 15);      // chunk stagger
    unsigned* bar = &g_bar[grp * 32];

    __nv_bfloat16* sWhi = (__nv_bfloat16*)(smem + SM_WHI);
    __nv_bfloat16* sWlo = (__nv_bfloat16*)(smem + SM_WLO);
    for (int idx = tid; idx < 32 * 1024; idx += 256) {
        int n = idx & 31, k = idx >> 5;
        sWhi[n * SW + k] = g_Whh_hi[(size_t)k * H_ + n0 + n];
        sWlo[n * SW + k] = g_Whh_lo[(size_t)k * H_ + n0 + n];
    }
    __syncthreads();

    const int a_row  = wm + ((lane >> 3) & 1) * 8 + (lane & 7);
    const uint32_t aoff = (uint32_t)(a_row * SA_R + (lane >> 4) * 8) * 2;
    const int b_n = wn + (lane >> 4) * 8 + (lane & 7);
    const uint32_t bW = sb + SM_WHI + (uint32_t)(b_n * SW + ((lane >> 3) & 1) * 8) * 2;

    // P prefetch for t = 0
    float2 pre[2][2];
    {
        const float* Pt = g_P;
#pragma unroll
        for (int nf = 0; nf < 2; nf++)
#pragma unroll
            for (int half = 0; half < 2; half++) {
                int rr = m0 + wm + g + half * 8;
                int cc = n0 + wn + nf * 8 + tg * 2;
                pre[nf][half] = *(const float2*)(Pt + (size_t)rr * H_ + cc);
            }
    }

    for (int t = 0; t < T_; t++) {
        const __nv_bfloat16* bHi = g_Hhi + (size_t)t * BH + (size_t)m0 * H_;
        const __nv_bfloat16* bLo = g_Hlo + (size_t)t * BH + (size_t)m0 * H_;

        float acc[3][2][4];
#pragma unroll
        for (int q = 0; q < 3; q++)
#pragma unroll
            for (int a = 0; a < 2; a++)
#pragma unroll
                for (int c = 0; c < 4; c++) acc[q][a][c] = 0.f;

        // prologue: chunks off, off+1 into stages 0, 1
#pragma unroll
        for (int pk = 0; pk < 2; pk++) {
            int cl = (pk + off) & 15;
#pragma unroll
            for (int j = 0; j < 4; j++) {
                int idx = j * 256 + tid;
                int plane = idx >> 9, rem = idx & 511;
                int r = rem >> 3, q8 = rem & 7;
                const __nv_bfloat16* src =
                    (plane ? bLo : bHi) + (size_t)r * H_ + cl * KT + q8 * 8;
                cpasync16(sb + SM_ABASE + pk * A_STAGE + plane * A_PLANE +
                          (uint32_t)(r * SA_R + q8 * 8) * 2, src);
            }
            cp_commit();
        }

        for (int kt = 0; kt < NKT; kt++) {
            int s = kt % 3;
            if (kt == NKT - 1) cp_wait<0>(); else cp_wait<1>();
            __syncthreads();

            if (kt + 2 < NKT) {
                int s2 = (kt + 2) % 3;
                int cl = (kt + 2 + off) & 15;
#pragma unroll
                for (int j = 0; j < 4; j++) {
                    int idx = j * 256 + tid;
                    int plane = idx >> 9, rem = idx & 511;
                    int r = rem >> 3, q8 = rem & 7;
                    const __nv_bfloat16* src =
                        (plane ? bLo : bHi) + (size_t)r * H_ + cl * KT + q8 * 8;
                    cpasync16(sb + SM_ABASE + s2 * A_STAGE + plane * A_PLANE +
                              (uint32_t)(r * SA_R + q8 * 8) * 2, src);
                }
                cp_commit();
            }

            int cl = (kt + off) & 15;
            uint32_t aHi = sb + SM_ABASE + s * A_STAGE + aoff;
            uint32_t aLo = aHi + A_PLANE;
            uint32_t bA  = bW + (uint32_t)(cl * KT) * 2;
#pragma unroll
            for (int ks = 0; ks < KT; ks += 16) {
                uint32_t ah[4], al[4], bh[4], bl[4];
                ldsm_x4(ah, aHi + ks * 2);
                ldsm_x4(al, aLo + ks * 2);
                ldsm_x4(bh, bA + ks * 2);
                ldsm_x4(bl, bA + ks * 2 + (uint32_t)(SM_WLO - SM_WHI));
                mma_bf16(acc[0][0], ah, bh + 0);
                mma_bf16(acc[0][1], ah, bh + 2);
                mma_bf16(acc[1][0], ah, bl + 0);
                mma_bf16(acc[1][1], ah, bl + 2);
                mma_bf16(acc[2][0], al, bh + 0);
                mma_bf16(acc[2][1], al, bh + 2);
            }
        }

        // epilogue: merge banks, add P, tanh, split-store into slot t+1
        __nv_bfloat16* oHi = g_Hhi + (size_t)(t + 1) * BH;
        __nv_bfloat16* oLo = g_Hlo + (size_t)(t + 1) * BH;
#pragma unroll
        for (int nf = 0; nf < 2; nf++)
#pragma unroll
            for (int half = 0; half < 2; half++) {
                int rr = m0 + wm + g + half * 8;
                int cc = n0 + wn + nf * 8 + tg * 2;
                float2 p = pre[nf][half];
                float s0 = acc[0][nf][half * 2] + acc[1][nf][half * 2]
                         + acc[2][nf][half * 2] + p.x;
                float s1 = acc[0][nf][half * 2 + 1] + acc[1][nf][half * 2 + 1]
                         + acc[2][nf][half * 2 + 1] + p.y;
                float h0v = tanhf(s0), h1v = tanhf(s1);
                __nv_bfloat16 h0h = __float2bfloat16(h0v);
                __nv_bfloat16 h1h = __float2bfloat16(h1v);
                __nv_bfloat162 hhi; hhi.x = h0h; hhi.y = h1h;
                __nv_bfloat162 hlo;
                hlo.x = __float2bfloat16(h0v - __bfloat162float(h0h));
                hlo.y = __float2bfloat16(h1v - __bfloat162float(h1h));
                *(__nv_bfloat162*)(oHi + (size_t)rr * H_ + cc) = hhi;
                *(__nv_bfloat162*)(oLo + (size_t)rr * H_ + cc) = hlo;
            }

        // barrier: publish stores (syncthreads + release arrive), prefetch P
        // for t+1 while waiting, then acquire-spin.
        __syncthreads();
        if (tid == 0) red_release_add(bar);
        {
            int tn = (t + 1 < T_) ? (t + 1) : t;
            const float* Pt = g_P + (size_t)tn * BH;
#pragma unroll
            for (int nf = 0; nf < 2; nf++)
#pragma unroll
                for (int half = 0; half < 2; half++) {
                    int rr = m0 + wm + g + half * 8;
                    int cc = n0 + wn + nf * 8 + tg * 2;
                    pre[nf][half] = *(const float2*)(Pt + (size_t)rr * H_ + cc);
                }
        }
        if (tid == 0) {
            unsigned target = 32u * (unsigned)(t + 1);
            while (ld_acquire(bar) < target) __nanosleep(32);
        }
        __syncthreads();
    }
}

// ---------------- split / misc kernels -------------------------------------
__device__ __forceinline__ void split1(float v, __nv_bfloat16* hi, __nv_bfloat16* lo) {
    __nv_bfloat16 h = __float2bfloat16(v);
    *hi = h;
    *lo = __float2bfloat16(v - __bfloat162float(h));
}

// weights + h0 split + barrier reset, one kernel
__global__ void split_all_kernel(const float* __restrict__ wxh,
                                 const float* __restrict__ whh,
                                 const float* __restrict__ why,
                                 const float* __restrict__ h0)
{
    if (blockIdx.x == 0 && threadIdx.x < 4) g_bar[threadIdx.x * 32] = 0;
    int i = blockIdx.x * 256 + threadIdx.x;
    const int N1 = D_ * H_;
    const int N2 = N1 + H_ * H_;
    const int N3 = N2 + H_ * O_;
    const int N4 = N3 + BH;
    if (i < N1)      split1(wxh[i],      &g_Wxh_hi[i],      &g_Wxh_lo[i]);
    else if (i < N2) split1(whh[i - N1], &g_Whh_hi[i - N1], &g_Whh_lo[i - N1]);
    else if (i < N3) split1(why[i - N2], &g_Why_hi[i - N2], &g_Why_lo[i - N2]);
    else if (i < N4) split1(h0[i - N3],  &g_Hhi[i - N3],    &g_Hlo[i - N3]);
}

__global__ void split_X_kernel(const float* __restrict__ x)
{
    size_t i = (size_t)blockIdx.x * 256 + threadIdx.x;
    if (i < BTD) split1(x[i], &g_Xhi[i], &g_Xlo[i]);
}

__global__ void final_h_kernel(float* __restrict__ out)
{
    int i = blockIdx.x * 256 + threadIdx.x;
    if (i < BH) {
        size_t o = (size_t)T_ * BH + i;
        out[BTO + i] = __bfloat162float(g_Hhi[o]) + __bfloat162float(g_Hlo[o]);
    }
}

// ---------------- launch ---------------------------------------------------
extern "C" void kernel_launch(void* const* d_in, const int* in_sizes, int n_in,
                              void* d_out, int out_size)
{
    (void)in_sizes; (void)n_in; (void)out_size;
    const float* x    = (const float*)d_in[0];
    const float* h0   = (const float*)d_in[1];
    const float* w_xh = (const float*)d_in[2];
    const float* w_hh = (const float*)d_in[3];
    const float* w_hy = (const float*)d_in[4];
    float* out = (float*)d_out;

    cudaFuncSetAttribute(rnn_persistent_kernel,
                         cudaFuncAttributeMaxDynamicSharedMemorySize, SMEM_RNN);
    cudaFuncSetAttribute(gemm_P_kernel,
                         cudaFuncAttributeMaxDynamicSharedMemorySize, SMEM_G);
    cudaFuncSetAttribute(gemm_Y_kernel,
                         cudaFuncAttributeMaxDynamicSharedMemorySize, SMEM_G);

    // 0: weights + h0 splits (+barrier reset)
    {
        int total = D_ * H_ + H_ * H_ + H_ * O_ + BH;
        split_all_kernel<<<(total + 255) / 256, 256>>>(w_xh, w_hh, w_hy, h0);
    }
    // 1: X split
    split_X_kernel<<<(int)((BTD + 255) / 256), 256>>>(x);
    // 2: P = X @ W_xh  (layout [t][b][h])
    gemm_P_kernel<<<dim3(H_ / 128, (B_ * T_) / 128), 256, SMEM_G>>>();
    // 3: persistent recurrence
    rnn_persistent_kernel<<<128, 256, SMEM_RNN>>>();
    // 4: Y = H_all @ W_hy
    gemm_Y_kernel<<<dim3(O_ / 128, (B_ * T_) / 128), 256, SMEM_G>>>(out);
    // 5: final h
    final_h_kernel<<<(BH + 255) / 256, 256>>>(out);
}